// round 4
// baseline (speedup 1.0000x reference)
#include <cuda_runtime.h>
#include <math.h>
#include <stdint.h>

// ---------------- problem constants ----------------
#define BB   16
#define TT   32
#define NN_  512
#define CC   128
#define HH   128
#define HLL  512
#define G4   (4*HLL)        // 2048
#define DD   (NN_*HH)       // 65536
#define TNH  ((long)TT*NN_*HH)   // 2,097,152  (per-batch stride)
#define EPSN 1e-5f
#define SPLITK0 8
#define LBLK 128
#define LTHR 256

// ---------------- device scratch ----------------
__device__ float g_d[NN_];
__device__ float g_M[NN_*NN_];
__device__ float g_hw [BB*TT*NN_*HH];      // also reused as split-K partial buffer
__device__ float g_tmp[BB*TT*NN_*HH];
__device__ float g_h1 [BB*TT*NN_*HH];
__device__ float g_h2 [BB*TT*NN_*HH];
__device__ float g_Z0[(long)BB*TT*G4];
__device__ float g_Z1[(long)BB*TT*G4];
__device__ float g_y0[(long)BB*TT*HLL];
__device__ float g_hA0[BB*HLL], g_hB0[BB*HLL];
__device__ float g_hA1[BB*HLL], g_hB1[BB*HLL];
__device__ unsigned g_bars[2];

// ---------------- helpers ----------------
__device__ __forceinline__ float sigf(float x) { return 1.0f/(1.0f+expf(-x)); }
__device__ __forceinline__ uint32_t f2tf32(float f) {
    uint32_t u;
    asm("cvt.rna.tf32.f32 %0, %1;" : "=r"(u) : "f"(f));
    return u;
}

// ---------------- graph normalization matrix ----------------
__global__ void deg_kernel(const float* __restrict__ adj, float* __restrict__ d) {
    int i = blockIdx.x*blockDim.x + threadIdx.x;
    if (i < NN_) {
        float s = 1.0f;                       // self loop
        for (int j = 0; j < NN_; j++) s += adj[(long)j*NN_ + i];
        d[i] = rsqrtf(s);
    }
}
__global__ void buildM_kernel(const float* __restrict__ adj, const float* __restrict__ d,
                              float* __restrict__ M) {
    int idx = blockIdx.x*blockDim.x + threadIdx.x;
    if (idx < NN_*NN_) {
        int j = idx >> 9, i = idx & (NN_-1);
        float a = adj[idx] + (i == j ? 1.0f : 0.0f);
        M[idx] = d[j]*a*d[i];
    }
}

// ============================================================================
// TF32 tensor-core GEMM. CTA tile 128x128x16, 8 warps of 64x32.
// Conflict-free smem: stride 136 (mod 32 == 8) for fragment loads; transpose
// stores use kq-major thread mapping so each warp stores consecutive m.
// ============================================================================
#define BM 128
#define BN 128
#define BK 16
#define ASTRIDE (BM+8)
#define BSTRIDE (BN+8)

template<bool BT_>
__global__ void __launch_bounds__(256, 2)
mma_gemm(const float* __restrict__ Ab, const float* __restrict__ Bb,
         const float* __restrict__ biasb, float* __restrict__ Cb,
         int M, int N, int K,
         long sA, int modA, long sB, int modB,
         long sBias, int modBias, long sC,
         int splitK, long sSplit)
{
    int z = blockIdx.z;
    int batch = z / splitK, split = z - batch*splitK;
    const float* A = Ab + (long)(batch % modA) * sA;
    const float* B = Bb + (long)(batch % modB) * sB;
    float* C = Cb + (long)batch * sC + (long)split * sSplit;
    const float* bias = biasb ? biasb + (long)(batch % modBias) * sBias : nullptr;

    int kchunk = K / splitK;
    int kbeg = split * kchunk;
    int nk = kchunk / BK;

    __shared__ uint32_t As[2][BK][ASTRIDE];
    __shared__ uint32_t Bs[2][BK][BSTRIDE];

    int tid = threadIdx.x;
    int lane = tid & 31;
    int warp = tid >> 5;
    int wm = (warp & 1) * 64;
    int wn = (warp >> 1) * 32;
    int m0 = blockIdx.y * BM;
    int n0 = blockIdx.x * BN;

    float acc[4][4][4];
    #pragma unroll
    for (int i = 0; i < 4; i++)
        #pragma unroll
        for (int j = 0; j < 4; j++)
            #pragma unroll
            for (int k = 0; k < 4; k++) acc[i][j][k] = 0.0f;

    // A loader: kq-major mapping -> warp-uniform kq, consecutive m (conflict-free STS)
    int a_m[2], a_kq[2];
    #pragma unroll
    for (int i = 0; i < 2; i++) { int idx = tid + i*256; a_kq[i] = idx >> 7; a_m[i] = idx & 127; }
    // B loader: BT path same kq-major mapping; NN path row-major (STS.128, conflict-free)
    int b_i0[2], b_i1[2];
    #pragma unroll
    for (int i = 0; i < 2; i++) {
        int idx = tid + i*256;
        if (BT_) { b_i1[i] = idx >> 7; b_i0[i] = idx & 127; }  // kq, n
        else     { b_i0[i] = idx >> 5; b_i1[i] = idx & 31; }   // r, cq
    }

    float4 ar[2], br[2];

    auto load_tile = [&](int kt) {
        int kg = kbeg + kt*BK;
        #pragma unroll
        for (int i = 0; i < 2; i++)
            ar[i] = *(const float4*)&A[(long)(m0 + a_m[i])*K + kg + a_kq[i]*4];
        #pragma unroll
        for (int i = 0; i < 2; i++) {
            if (BT_) br[i] = *(const float4*)&B[(long)(n0 + b_i0[i])*K + kg + b_i1[i]*4];
            else     br[i] = *(const float4*)&B[(long)(kg + b_i0[i])*N + n0 + b_i1[i]*4];
        }
    };
    auto store_tile = [&](int buf) {
        #pragma unroll
        for (int i = 0; i < 2; i++) {
            int m = a_m[i], kq = a_kq[i];
            As[buf][kq*4+0][m] = f2tf32(ar[i].x);
            As[buf][kq*4+1][m] = f2tf32(ar[i].y);
            As[buf][kq*4+2][m] = f2tf32(ar[i].z);
            As[buf][kq*4+3][m] = f2tf32(ar[i].w);
        }
        #pragma unroll
        for (int i = 0; i < 2; i++) {
            if (BT_) {
                int n = b_i0[i], kq = b_i1[i];
                Bs[buf][kq*4+0][n] = f2tf32(br[i].x);
                Bs[buf][kq*4+1][n] = f2tf32(br[i].y);
                Bs[buf][kq*4+2][n] = f2tf32(br[i].z);
                Bs[buf][kq*4+3][n] = f2tf32(br[i].w);
            } else {
                int r = b_i0[i], c = b_i1[i]*4;
                uint4 v;
                v.x = f2tf32(br[i].x); v.y = f2tf32(br[i].y);
                v.z = f2tf32(br[i].z); v.w = f2tf32(br[i].w);
                *(uint4*)&Bs[buf][r][c] = v;
            }
        }
    };

    load_tile(0);
    store_tile(0);
    __syncthreads();

    int lk = lane & 3, lg = lane >> 2;

    for (int kt = 0; kt < nk; kt++) {
        int cur = kt & 1;
        if (kt + 1 < nk) load_tile(kt + 1);

        #pragma unroll
        for (int ks = 0; ks < 2; ks++) {
            uint32_t af[4][4];
            #pragma unroll
            for (int mt = 0; mt < 4; mt++) {
                int mb = wm + mt*16;
                af[mt][0] = As[cur][ks*8 + lk    ][mb + lg    ];
                af[mt][1] = As[cur][ks*8 + lk    ][mb + lg + 8];
                af[mt][2] = As[cur][ks*8 + lk + 4][mb + lg    ];
                af[mt][3] = As[cur][ks*8 + lk + 4][mb + lg + 8];
            }
            uint32_t bf[4][2];
            #pragma unroll
            for (int nt = 0; nt < 4; nt++) {
                int nb = wn + nt*8;
                bf[nt][0] = Bs[cur][ks*8 + lk    ][nb + lg];
                bf[nt][1] = Bs[cur][ks*8 + lk + 4][nb + lg];
            }
            #pragma unroll
            for (int mt = 0; mt < 4; mt++)
                #pragma unroll
                for (int nt = 0; nt < 4; nt++) {
                    asm volatile(
                        "mma.sync.aligned.m16n8k8.row.col.f32.tf32.tf32.f32 "
                        "{%0,%1,%2,%3}, {%4,%5,%6,%7}, {%8,%9}, {%0,%1,%2,%3};"
                        : "+f"(acc[mt][nt][0]), "+f"(acc[mt][nt][1]),
                          "+f"(acc[mt][nt][2]), "+f"(acc[mt][nt][3])
                        : "r"(af[mt][0]), "r"(af[mt][1]), "r"(af[mt][2]), "r"(af[mt][3]),
                          "r"(bf[nt][0]), "r"(bf[nt][1]));
                }
        }

        if (kt + 1 < nk) {
            store_tile((kt + 1) & 1);
            __syncthreads();
        }
    }

    #pragma unroll
    for (int nt = 0; nt < 4; nt++) {
        int c0 = n0 + wn + nt*8 + 2*lk;
        float bv0 = bias ? bias[c0] : 0.0f;
        float bv1 = bias ? bias[c0+1] : 0.0f;
        #pragma unroll
        for (int mt = 0; mt < 4; mt++) {
            int r = m0 + wm + mt*16 + lg;
            float2 v0 = make_float2(acc[mt][nt][0] + bv0, acc[mt][nt][1] + bv1);
            float2 v1 = make_float2(acc[mt][nt][2] + bv0, acc[mt][nt][3] + bv1);
            *(float2*)&C[(long)r*N + c0] = v0;
            *(float2*)&C[(long)(r+8)*N + c0] = v1;
        }
    }
}

// ---------------- split-K reduce + bias ----------------
__global__ void reduce_bias_kernel(const float* __restrict__ P, const float* __restrict__ bias,
                                   float* __restrict__ Z, long total, long stride, int splits)
{
    long idx = (long)blockIdx.x*blockDim.x + threadIdx.x;
    if (idx >= total) return;
    float s = bias[idx & (G4-1)];
    #pragma unroll 8
    for (int i = 0; i < splits; i++) s += P[(long)i*stride + idx];
    Z[idx] = s;
}

// ---------------- GraphNorm + residual + ReLU ----------------
__global__ void graphnorm_kernel(const float* __restrict__ hraw, const float* __restrict__ res,
                                 const float* __restrict__ w, const float* __restrict__ bias,
                                 const float* __restrict__ ms, float* __restrict__ out)
{
    long p = (long)blockIdx.x*blockDim.x + threadIdx.x;
    if (p >= TNH) return;
    int h = (int)(p & (HH-1));
    float v[BB];
    float mean = 0.0f;
    #pragma unroll
    for (int b = 0; b < BB; b++) { v[b] = hraw[(long)b*TNH + p]; mean += v[b]; }
    mean *= (1.0f/BB);
    float msv = ms[h], var = 0.0f;
    #pragma unroll
    for (int b = 0; b < BB; b++) { v[b] -= msv*mean; var += v[b]*v[b]; }
    var *= (1.0f/BB);
    float inv = rsqrtf(var + EPSN);
    float wv = w[h]*inv, bv = bias[h];
    #pragma unroll
    for (int b = 0; b < BB; b++) {
        float r = wv*v[b] + bv + res[(long)b*TNH + p];
        out[(long)b*TNH + p] = fmaxf(r, 0.0f);
    }
}

// ---------------- zero barrier counters ----------------
__global__ void zero_bars_kernel(unsigned* bars) {
    if (threadIdx.x < 2) bars[threadIdx.x] = 0u;
}

// ============================================================================
// Persistent LSTM layer (see R3). 128 blocks x 256 thr, weights in registers.
// ============================================================================
template<bool WRITE_Y>
__global__ void __launch_bounds__(LTHR, 1)
lstm_persistent(const float* __restrict__ Z,
                const float* __restrict__ Whh,
                const float* __restrict__ bhh,
                float* __restrict__ bufA, float* __restrict__ bufB,
                float* __restrict__ y,
                unsigned* __restrict__ bar)
{
    __shared__ float hs[HLL][BB];
    __shared__ float red[8*16*17];
    __shared__ float gsum[16*16];

    const int t = threadIdx.x;
    const int blk = blockIdx.x;
    const int c = t & 15, sub = t >> 4;
    const int warp = t >> 5;
    const int mh_local = c & 3, gate = c >> 2;
    const int m = gate*HLL + blk*4 + mh_local;

    float w[32];
    {
        const float* wr = Whh + (long)m*HLL + sub*32;
        #pragma unroll
        for (int j = 0; j < 32; j++) w[j] = wr[j];
    }

    const int ub = t & 15;
    const int uml = (t >> 4) & 3;
    const int umh = blk*4 + uml;
    float creg = 0.0f;
    float bi = 0.f, bf = 0.f, bg = 0.f, bo = 0.f;
    if (t < 64) {
        bi = bhh[0*HLL + umh]; bf = bhh[1*HLL + umh];
        bg = bhh[2*HLL + umh]; bo = bhh[3*HLL + umh];
    }

    for (int i = t; i < HLL*BB; i += LTHR) (&hs[0][0])[i] = 0.0f;
    __syncthreads();

    unsigned target = 0;

    for (int step = 0; step < TT; step++) {
        float zi = 0.f, zf = 0.f, zg = 0.f, zo = 0.f;
        if (t < 64) {
            long zb = ((long)ub*TT + step)*G4;
            zi = Z[zb + 0*HLL + umh]; zf = Z[zb + 1*HLL + umh];
            zg = Z[zb + 2*HLL + umh]; zo = Z[zb + 3*HLL + umh];
        }

        float acc[BB];
        #pragma unroll
        for (int b = 0; b < BB; b++) acc[b] = 0.0f;
        #pragma unroll
        for (int j = 0; j < 32; j++) {
            float wv = w[j];
            const float* hr = &hs[sub*32 + j][0];
            #pragma unroll
            for (int b = 0; b < BB; b += 4) {
                float4 h4 = *(const float4*)&hr[b];
                acc[b+0] += wv*h4.x; acc[b+1] += wv*h4.y;
                acc[b+2] += wv*h4.z; acc[b+3] += wv*h4.w;
            }
        }
        #pragma unroll
        for (int b = 0; b < BB; b++)
            acc[b] += __shfl_down_sync(0xffffffffu, acc[b], 16);
        if ((t & 31) < 16) {
            float* rp = &red[(warp*16 + c)*17];
            #pragma unroll
            for (int b = 0; b < BB; b++) rp[b] = acc[b];
        }
        __syncthreads();
        {
            int c2 = t & 15, b2 = t >> 4;
            float s = 0.0f;
            #pragma unroll
            for (int s2 = 0; s2 < 8; s2++) s += red[(s2*16 + c2)*17 + b2];
            gsum[c2*16 + b2] = s;
        }
        __syncthreads();

        if (t < 64) {
            float gi = sigf (zi + gsum[(0*4+uml)*16 + ub] + bi);
            float gf = sigf (zf + gsum[(1*4+uml)*16 + ub] + bf);
            float gg = tanhf(zg + gsum[(2*4+uml)*16 + ub] + bg);
            float go = sigf (zo + gsum[(3*4+uml)*16 + ub] + bo);
            creg = gf*creg + gi*gg;
            float hn = go*tanhf(creg);
            float* hout = ((step+1) & 1) ? bufB : bufA;
            hout[ub*HLL + umh] = hn;
            if (WRITE_Y) y[((long)ub*TT + step)*HLL + umh] = hn;
            __threadfence();
        }
        __syncthreads();

        target += LBLK;
        if (t == 0) {
            atomicAdd(bar, 1u);
            while (*(volatile unsigned*)bar < target) { }
        }
        __syncthreads();
        __threadfence();

        if (step + 1 < TT) {
            const float* hin = ((step+1) & 1) ? bufB : bufA;
            for (int i = t; i < BB*HLL; i += LTHR) {
                int b = i >> 9, j = i & (HLL-1);
                hs[j][b] = hin[i];
            }
            __syncthreads();
        }
    }
}

// ---------------- final projection ----------------
__global__ void proj_kernel(const float* __restrict__ h, const float* __restrict__ Wp,
                            const float* __restrict__ bp, float* __restrict__ out)
{
    int tid = threadIdx.x;
    int b = tid >> 3, o = tid & 7;
    float s = bp[o];
    const float* wr = Wp + o*HLL;
    const float* hr = h  + b*HLL;
    for (int m = 0; m < HLL; m++) s += hr[m]*wr[m];
    out[b*8 + o] = s;
}

// ---------------- launch ----------------
extern "C" void kernel_launch(void* const* d_in, const int* in_sizes, int n_in,
                              void* d_out, int out_size)
{
    const float* x    = (const float*)d_in[0];
    const float* adj  = (const float*)d_in[1];
    const float* W1   = (const float*)d_in[2];
    const float* b1   = (const float*)d_in[3];
    const float* W2   = (const float*)d_in[4];
    const float* b2   = (const float*)d_in[5];
    const float* gn1w = (const float*)d_in[6];
    const float* gn1b = (const float*)d_in[7];
    const float* gn1m = (const float*)d_in[8];
    const float* gn2w = (const float*)d_in[9];
    const float* gn2b = (const float*)d_in[10];
    const float* gn2m = (const float*)d_in[11];
    const float* Wih0 = (const float*)d_in[12];
    const float* Whh0 = (const float*)d_in[13];
    const float* bih0 = (const float*)d_in[14];
    const float* bhh0 = (const float*)d_in[15];
    const float* Wih1 = (const float*)d_in[16];
    const float* Whh1 = (const float*)d_in[17];
    const float* bih1 = (const float*)d_in[18];
    const float* bhh1 = (const float*)d_in[19];
    const float* Wp   = (const float*)d_in[20];
    const float* bp   = (const float*)d_in[21];
    float* out = (float*)d_out;

    float *pM, *pD, *pHw, *pTmp, *pH1, *pH2, *pZ0, *pZ1, *pY0;
    float *pHA0, *pHB0, *pHA1, *pHB1;
    unsigned* pBars;
    cudaGetSymbolAddress((void**)&pD,   g_d);
    cudaGetSymbolAddress((void**)&pM,   g_M);
    cudaGetSymbolAddress((void**)&pHw,  g_hw);
    cudaGetSymbolAddress((void**)&pTmp, g_tmp);
    cudaGetSymbolAddress((void**)&pH1,  g_h1);
    cudaGetSymbolAddress((void**)&pH2,  g_h2);
    cudaGetSymbolAddress((void**)&pZ0,  g_Z0);
    cudaGetSymbolAddress((void**)&pZ1,  g_Z1);
    cudaGetSymbolAddress((void**)&pY0,  g_y0);
    cudaGetSymbolAddress((void**)&pHA0, g_hA0);
    cudaGetSymbolAddress((void**)&pHB0, g_hB0);
    cudaGetSymbolAddress((void**)&pHA1, g_hA1);
    cudaGetSymbolAddress((void**)&pHB1, g_hB1);
    cudaGetSymbolAddress((void**)&pBars, g_bars);

    deg_kernel<<<2, 256>>>(adj, pD);
    buildM_kernel<<<(NN_*NN_)/256, 256>>>(adj, pD, pM);
    zero_bars_kernel<<<1, 32>>>(pBars);

    const long sX = (long)NN_*HH;
    const int  BT = BB*TT;

    // ---- GCN layer 1 ----
    mma_gemm<false><<<dim3(HH/BN, NN_/BM, BT), 256>>>(x, W1, nullptr, pHw,
        NN_, HH, CC, sX, BT, (long)CC*HH, TT, 0, 1, sX, 1, 0);
    mma_gemm<false><<<dim3(HH/BN, NN_/BM, BT), 256>>>(pM, pHw, b1, pTmp,
        NN_, HH, NN_, 0, 1, sX, BT, HH, TT, sX, 1, 0);
    graphnorm_kernel<<<(int)(TNH/256), 256>>>(pTmp, x, gn1w, gn1b, gn1m, pH1);

    // ---- GCN layer 2 ----
    mma_gemm<false><<<dim3(HH/BN, NN_/BM, BT), 256>>>(pH1, W2, nullptr, pHw,
        NN_, HH, HH, sX, BT, (long)HH*HH, TT, 0, 1, sX, 1, 0);
    mma_gemm<false><<<dim3(HH/BN, NN_/BM, BT), 256>>>(pM, pHw, b2, pTmp,
        NN_, HH, NN_, 0, 1, sX, BT, HH, TT, sX, 1, 0);
    graphnorm_kernel<<<(int)(TNH/256), 256>>>(pTmp, pH1, gn2w, gn2b, gn2m, pH2);

    // ---- LSTM layer 0 ----
    const long zTot = (long)BT*G4;
    mma_gemm<true><<<dim3(G4/BN, BT/BM, SPLITK0), 256>>>(pH2, Wih0, nullptr, pHw,
        BT, G4, DD, 0, 1, 0, 1, 0, 1, 0, SPLITK0, zTot);
    reduce_bias_kernel<<<(int)(zTot/256), 256>>>(pHw, bih0, pZ0, zTot, zTot, SPLITK0);
    lstm_persistent<true><<<LBLK, LTHR>>>(pZ0, Whh0, bhh0, pHA0, pHB0, pY0, pBars + 0);

    // ---- LSTM layer 1 ----
    mma_gemm<true><<<dim3(G4/BN, BT/BM, 1), 256>>>(pY0, Wih1, bih1, pZ1,
        BT, G4, HLL, 0, 1, 0, 1, 0, 1, 0, 1, 0);
    lstm_persistent<false><<<LBLK, LTHR>>>(pZ1, Whh1, bhh1, pHA1, pHB1, nullptr, pBars + 1);

    // ---- projection ----
    proj_kernel<<<1, 128>>>(pHA1, Wp, bp, out);
}

// round 5
// speedup vs baseline: 1.4946x; 1.4946x over previous
#include <cuda_runtime.h>
#include <math.h>
#include <stdint.h>

// ---------------- problem constants ----------------
#define BB   16
#define TT   32
#define NN_  512
#define CC   128
#define HH   128
#define HLL  512
#define G4   (4*HLL)        // 2048
#define DD   (NN_*HH)       // 65536
#define TNH  ((long)TT*NN_*HH)   // 2,097,152
#define EPSN 1e-5f
#define SPLITK0 8
#define SPLITK1 4
#define LBLK 128
#define LTHR 256

// ---------------- device scratch ----------------
__device__ float g_d[NN_];
__device__ float g_M[NN_*NN_];
__device__ float g_hw [BB*TT*NN_*HH];      // also split-K partial buffer (Z0)
__device__ float g_tmp[BB*TT*NN_*HH];      // also split-K partial buffer (Z1)
__device__ float g_h1 [BB*TT*NN_*HH];
__device__ float g_h2 [BB*TT*NN_*HH];
__device__ float g_Z0[(long)BB*TT*G4];
__device__ float g_Z1[(long)BB*TT*G4];
__device__ float g_y0[(long)BB*TT*HLL];
__device__ float g_hA0[BB*HLL], g_hB0[BB*HLL];
__device__ float g_hA1[BB*HLL], g_hB1[BB*HLL];
__device__ unsigned g_bars[2];

// ---------------- helpers ----------------
__device__ __forceinline__ float sigf(float x) { return 1.0f/(1.0f+expf(-x)); }
__device__ __forceinline__ uint32_t f2tf32(float f) {
    uint32_t u;
    asm("cvt.rna.tf32.f32 %0, %1;" : "=r"(u) : "f"(f));
    return u;
}
__device__ __forceinline__ uint4 cvt4(float4 v) {
    uint4 r;
    r.x = f2tf32(v.x); r.y = f2tf32(v.y); r.z = f2tf32(v.z); r.w = f2tf32(v.w);
    return r;
}

// ---------------- graph normalization matrix ----------------
__global__ void deg_kernel(const float* __restrict__ adj, float* __restrict__ d) {
    int i = blockIdx.x*blockDim.x + threadIdx.x;
    if (i < NN_) {
        float s = 1.0f;
        for (int j = 0; j < NN_; j++) s += adj[(long)j*NN_ + i];
        d[i] = rsqrtf(s);
    }
}
__global__ void buildM_kernel(const float* __restrict__ adj, const float* __restrict__ d,
                              float* __restrict__ M) {
    int idx = blockIdx.x*blockDim.x + threadIdx.x;
    if (idx < NN_*NN_) {
        int j = idx >> 9, i = idx & (NN_-1);
        float a = adj[idx] + (i == j ? 1.0f : 0.0f);
        M[idx] = d[j]*a*d[i];
    }
}

// ============================================================================
// TF32 tensor-core GEMM. CTA tile 256x128x16, 16 warps of 64x32, 512 threads.
// Row-major padded smem: A[m][20], B-BT[n][20], B-NN[k][136].
// LDG coalesced, STS 128-bit direct, LDS conflict-free.
// ============================================================================
#define BM 256
#define BN 128
#define BK 16
#define KP 20
#define BSN 136
#define GTHR 512
#define SMEM_A_WORDS (2*BM*KP)                    // 10240
#define SMEM_B_WORDS (2*BN*KP > 2*BK*BSN ? 2*BN*KP : 2*BK*BSN)  // 5120
#define SMEM_BYTES ((SMEM_A_WORDS + SMEM_B_WORDS)*4)            // 61440

extern __shared__ uint32_t smem_dyn[];

template<bool BT_>
__global__ void __launch_bounds__(GTHR, 1)
mma_gemm(const float* __restrict__ Ab, const float* __restrict__ Bb,
         const float* __restrict__ biasb, float* __restrict__ Cb,
         int M, int N, int K,
         long sA, int modA, long sB, int modB,
         long sBias, int modBias, long sC,
         int splitK, long sSplit)
{
    int z = blockIdx.z;
    int batch = z / splitK, split = z - batch*splitK;
    const float* A = Ab + (long)(batch % modA) * sA;
    const float* B = Bb + (long)(batch % modB) * sB;
    float* C = Cb + (long)batch * sC + (long)split * sSplit;
    const float* bias = biasb ? biasb + (long)(batch % modBias) * sBias : nullptr;

    int kchunk = K / splitK;
    int kbeg = split * kchunk;
    int nk = kchunk / BK;

    uint32_t* AsB = smem_dyn;                  // [2][BM][KP]
    uint32_t* BsB = smem_dyn + SMEM_A_WORDS;   // [2][BN][KP] or [2][BK][BSN]

    int tid = threadIdx.x;
    int lane = tid & 31;
    int warp = tid >> 5;
    int wm = (warp & 3) * 64;
    int wn = (warp >> 2) * 32;
    int m0 = blockIdx.y * BM;
    int n0 = blockIdx.x * BN;

    float acc[4][4][4];
    #pragma unroll
    for (int i = 0; i < 4; i++)
        #pragma unroll
        for (int j = 0; j < 4; j++)
            #pragma unroll
            for (int k = 0; k < 4; k++) acc[i][j][k] = 0.0f;

    // A loader: 1024 uint4-chunks, 2/thread: m = idx>>2, kq = idx&3
    int a_m[2], a_kq[2];
    #pragma unroll
    for (int i = 0; i < 2; i++) { int idx = tid + i*GTHR; a_m[i] = idx >> 2; a_kq[i] = idx & 3; }
    // B loader: 512 chunks, 1/thread
    int b_i0, b_i1;
    if (BT_) { b_i0 = tid >> 2; b_i1 = tid & 3; }   // n, kq
    else     { b_i0 = tid >> 5; b_i1 = tid & 31; }  // r(k), cq

    float4 ar[2], br;

    auto load_tile = [&](int kt) {
        int kg = kbeg + kt*BK;
        #pragma unroll
        for (int i = 0; i < 2; i++)
            ar[i] = *(const float4*)&A[(long)(m0 + a_m[i])*K + kg + a_kq[i]*4];
        if (BT_) br = *(const float4*)&B[(long)(n0 + b_i0)*K + kg + b_i1*4];
        else     br = *(const float4*)&B[(long)(kg + b_i0)*N + n0 + b_i1*4];
    };
    auto store_tile = [&](int buf) {
        #pragma unroll
        for (int i = 0; i < 2; i++)
            *(uint4*)&AsB[(buf*BM + a_m[i])*KP + a_kq[i]*4] = cvt4(ar[i]);
        if (BT_) *(uint4*)&BsB[(buf*BN + b_i0)*KP + b_i1*4] = cvt4(br);
        else     *(uint4*)&BsB[(buf*BK + b_i0)*BSN + b_i1*4] = cvt4(br);
    };

    load_tile(0);
    store_tile(0);
    __syncthreads();

    int lk = lane & 3, lg = lane >> 2;

    for (int kt = 0; kt < nk; kt++) {
        int cur = kt & 1;
        if (kt + 1 < nk) load_tile(kt + 1);

        const uint32_t* Asc = AsB + cur*BM*KP;
        const uint32_t* Bsc = BsB + (BT_ ? cur*BN*KP : cur*BK*BSN);

        #pragma unroll
        for (int ks = 0; ks < 2; ks++) {
            int kb = ks*8;
            uint32_t af[4][4];
            #pragma unroll
            for (int mt = 0; mt < 4; mt++) {
                int mr = wm + mt*16 + lg;
                af[mt][0] = Asc[mr*KP + kb + lk];
                af[mt][1] = Asc[(mr+8)*KP + kb + lk];
                af[mt][2] = Asc[mr*KP + kb + lk + 4];
                af[mt][3] = Asc[(mr+8)*KP + kb + lk + 4];
            }
            uint32_t bf[4][2];
            #pragma unroll
            for (int nt = 0; nt < 4; nt++) {
                int nb = wn + nt*8;
                if (BT_) {
                    bf[nt][0] = Bsc[(nb+lg)*KP + kb + lk];
                    bf[nt][1] = Bsc[(nb+lg)*KP + kb + lk + 4];
                } else {
                    bf[nt][0] = Bsc[(kb+lk)*BSN + nb + lg];
                    bf[nt][1] = Bsc[(kb+lk+4)*BSN + nb + lg];
                }
            }
            #pragma unroll
            for (int mt = 0; mt < 4; mt++)
                #pragma unroll
                for (int nt = 0; nt < 4; nt++) {
                    asm volatile(
                        "mma.sync.aligned.m16n8k8.row.col.f32.tf32.tf32.f32 "
                        "{%0,%1,%2,%3}, {%4,%5,%6,%7}, {%8,%9}, {%0,%1,%2,%3};"
                        : "+f"(acc[mt][nt][0]), "+f"(acc[mt][nt][1]),
                          "+f"(acc[mt][nt][2]), "+f"(acc[mt][nt][3])
                        : "r"(af[mt][0]), "r"(af[mt][1]), "r"(af[mt][2]), "r"(af[mt][3]),
                          "r"(bf[nt][0]), "r"(bf[nt][1]));
                }
        }

        if (kt + 1 < nk) {
            store_tile((kt + 1) & 1);
            __syncthreads();
        }
    }

    #pragma unroll
    for (int nt = 0; nt < 4; nt++) {
        int c0 = n0 + wn + nt*8 + 2*lk;
        float bv0 = bias ? bias[c0] : 0.0f;
        float bv1 = bias ? bias[c0+1] : 0.0f;
        #pragma unroll
        for (int mt = 0; mt < 4; mt++) {
            int r = m0 + wm + mt*16 + lg;
            float2 v0 = make_float2(acc[mt][nt][0] + bv0, acc[mt][nt][1] + bv1);
            float2 v1 = make_float2(acc[mt][nt][2] + bv0, acc[mt][nt][3] + bv1);
            *(float2*)&C[(long)r*N + c0] = v0;
            *(float2*)&C[(long)(r+8)*N + c0] = v1;
        }
    }
}

// ---------------- split-K reduce + bias ----------------
__global__ void reduce_bias_kernel(const float* __restrict__ P, const float* __restrict__ bias,
                                   float* __restrict__ Z, long total, long stride, int splits)
{
    long idx = (long)blockIdx.x*blockDim.x + threadIdx.x;
    if (idx >= total) return;
    float s = bias[idx & (G4-1)];
    #pragma unroll 8
    for (int i = 0; i < splits; i++) s += P[(long)i*stride + idx];
    Z[idx] = s;
}

// ---------------- GraphNorm + residual + ReLU ----------------
__global__ void graphnorm_kernel(const float* __restrict__ hraw, const float* __restrict__ res,
                                 const float* __restrict__ w, const float* __restrict__ bias,
                                 const float* __restrict__ ms, float* __restrict__ out)
{
    long p = (long)blockIdx.x*blockDim.x + threadIdx.x;
    if (p >= TNH) return;
    int h = (int)(p & (HH-1));
    float v[BB];
    float mean = 0.0f;
    #pragma unroll
    for (int b = 0; b < BB; b++) { v[b] = hraw[(long)b*TNH + p]; mean += v[b]; }
    mean *= (1.0f/BB);
    float msv = ms[h], var = 0.0f;
    #pragma unroll
    for (int b = 0; b < BB; b++) { v[b] -= msv*mean; var += v[b]*v[b]; }
    var *= (1.0f/BB);
    float inv = rsqrtf(var + EPSN);
    float wv = w[h]*inv, bv = bias[h];
    #pragma unroll
    for (int b = 0; b < BB; b++) {
        float r = wv*v[b] + bv + res[(long)b*TNH + p];
        out[(long)b*TNH + p] = fmaxf(r, 0.0f);
    }
}

// ---------------- zero barrier counters ----------------
__global__ void zero_bars_kernel(unsigned* bars) {
    if (threadIdx.x < 2) bars[threadIdx.x] = 0u;
}

// ============================================================================
// Persistent LSTM layer (R3). 128 blocks x 256 thr, weights in registers.
// ============================================================================
template<bool WRITE_Y>
__global__ void __launch_bounds__(LTHR, 1)
lstm_persistent(const float* __restrict__ Z,
                const float* __restrict__ Whh,
                const float* __restrict__ bhh,
                float* __restrict__ bufA, float* __restrict__ bufB,
                float* __restrict__ y,
                unsigned* __restrict__ bar)
{
    __shared__ float hs[HLL][BB];
    __shared__ float red[8*16*17];
    __shared__ float gsum[16*16];

    const int t = threadIdx.x;
    const int blk = blockIdx.x;
    const int c = t & 15, sub = t >> 4;
    const int warp = t >> 5;
    const int mh_local = c & 3, gate = c >> 2;
    const int m = gate*HLL + blk*4 + mh_local;

    float w[32];
    {
        const float* wr = Whh + (long)m*HLL + sub*32;
        #pragma unroll
        for (int j = 0; j < 32; j++) w[j] = wr[j];
    }

    const int ub = t & 15;
    const int uml = (t >> 4) & 3;
    const int umh = blk*4 + uml;
    float creg = 0.0f;
    float bi = 0.f, bf = 0.f, bg = 0.f, bo = 0.f;
    if (t < 64) {
        bi = bhh[0*HLL + umh]; bf = bhh[1*HLL + umh];
        bg = bhh[2*HLL + umh]; bo = bhh[3*HLL + umh];
    }

    for (int i = t; i < HLL*BB; i += LTHR) (&hs[0][0])[i] = 0.0f;
    __syncthreads();

    unsigned target = 0;

    for (int step = 0; step < TT; step++) {
        float zi = 0.f, zf = 0.f, zg = 0.f, zo = 0.f;
        if (t < 64) {
            long zb = ((long)ub*TT + step)*G4;
            zi = Z[zb + 0*HLL + umh]; zf = Z[zb + 1*HLL + umh];
            zg = Z[zb + 2*HLL + umh]; zo = Z[zb + 3*HLL + umh];
        }

        float acc[BB];
        #pragma unroll
        for (int b = 0; b < BB; b++) acc[b] = 0.0f;
        #pragma unroll
        for (int j = 0; j < 32; j++) {
            float wv = w[j];
            const float* hr = &hs[sub*32 + j][0];
            #pragma unroll
            for (int b = 0; b < BB; b += 4) {
                float4 h4 = *(const float4*)&hr[b];
                acc[b+0] += wv*h4.x; acc[b+1] += wv*h4.y;
                acc[b+2] += wv*h4.z; acc[b+3] += wv*h4.w;
            }
        }
        #pragma unroll
        for (int b = 0; b < BB; b++)
            acc[b] += __shfl_down_sync(0xffffffffu, acc[b], 16);
        if ((t & 31) < 16) {
            float* rp = &red[(warp*16 + c)*17];
            #pragma unroll
            for (int b = 0; b < BB; b++) rp[b] = acc[b];
        }
        __syncthreads();
        {
            int c2 = t & 15, b2 = t >> 4;
            float s = 0.0f;
            #pragma unroll
            for (int s2 = 0; s2 < 8; s2++) s += red[(s2*16 + c2)*17 + b2];
            gsum[c2*16 + b2] = s;
        }
        __syncthreads();

        if (t < 64) {
            float gi = sigf (zi + gsum[(0*4+uml)*16 + ub] + bi);
            float gf = sigf (zf + gsum[(1*4+uml)*16 + ub] + bf);
            float gg = tanhf(zg + gsum[(2*4+uml)*16 + ub] + bg);
            float go = sigf (zo + gsum[(3*4+uml)*16 + ub] + bo);
            creg = gf*creg + gi*gg;
            float hn = go*tanhf(creg);
            float* hout = ((step+1) & 1) ? bufB : bufA;
            hout[ub*HLL + umh] = hn;
            if (WRITE_Y) y[((long)ub*TT + step)*HLL + umh] = hn;
            __threadfence();
        }
        __syncthreads();

        target += LBLK;
        if (t == 0) {
            atomicAdd(bar, 1u);
            while (*(volatile unsigned*)bar < target) { }
        }
        __syncthreads();
        __threadfence();

        if (step + 1 < TT) {
            const float* hin = ((step+1) & 1) ? bufB : bufA;
            for (int i = t; i < BB*HLL; i += LTHR) {
                int b = i >> 9, j = i & (HLL-1);
                hs[j][b] = hin[i];
            }
            __syncthreads();
        }
    }
}

// ---------------- final projection ----------------
__global__ void proj_kernel(const float* __restrict__ h, const float* __restrict__ Wp,
                            const float* __restrict__ bp, float* __restrict__ out)
{
    int tid = threadIdx.x;
    int b = tid >> 3, o = tid & 7;
    float s = bp[o];
    const float* wr = Wp + o*HLL;
    const float* hr = h  + b*HLL;
    for (int m = 0; m < HLL; m++) s += hr[m]*wr[m];
    out[b*8 + o] = s;
}

// ---------------- launch ----------------
extern "C" void kernel_launch(void* const* d_in, const int* in_sizes, int n_in,
                              void* d_out, int out_size)
{
    const float* x    = (const float*)d_in[0];
    const float* adj  = (const float*)d_in[1];
    const float* W1   = (const float*)d_in[2];
    const float* b1   = (const float*)d_in[3];
    const float* W2   = (const float*)d_in[4];
    const float* b2   = (const float*)d_in[5];
    const float* gn1w = (const float*)d_in[6];
    const float* gn1b = (const float*)d_in[7];
    const float* gn1m = (const float*)d_in[8];
    const float* gn2w = (const float*)d_in[9];
    const float* gn2b = (const float*)d_in[10];
    const float* gn2m = (const float*)d_in[11];
    const float* Wih0 = (const float*)d_in[12];
    const float* Whh0 = (const float*)d_in[13];
    const float* bih0 = (const float*)d_in[14];
    const float* bhh0 = (const float*)d_in[15];
    const float* Wih1 = (const float*)d_in[16];
    const float* Whh1 = (const float*)d_in[17];
    const float* bih1 = (const float*)d_in[18];
    const float* bhh1 = (const float*)d_in[19];
    const float* Wp   = (const float*)d_in[20];
    const float* bp   = (const float*)d_in[21];
    float* out = (float*)d_out;

    float *pM, *pD, *pHw, *pTmp, *pH1, *pH2, *pZ0, *pZ1, *pY0;
    float *pHA0, *pHB0, *pHA1, *pHB1;
    unsigned* pBars;
    cudaGetSymbolAddress((void**)&pD,   g_d);
    cudaGetSymbolAddress((void**)&pM,   g_M);
    cudaGetSymbolAddress((void**)&pHw,  g_hw);
    cudaGetSymbolAddress((void**)&pTmp, g_tmp);
    cudaGetSymbolAddress((void**)&pH1,  g_h1);
    cudaGetSymbolAddress((void**)&pH2,  g_h2);
    cudaGetSymbolAddress((void**)&pZ0,  g_Z0);
    cudaGetSymbolAddress((void**)&pZ1,  g_Z1);
    cudaGetSymbolAddress((void**)&pY0,  g_y0);
    cudaGetSymbolAddress((void**)&pHA0, g_hA0);
    cudaGetSymbolAddress((void**)&pHB0, g_hB0);
    cudaGetSymbolAddress((void**)&pHA1, g_hA1);
    cudaGetSymbolAddress((void**)&pHB1, g_hB1);
    cudaGetSymbolAddress((void**)&pBars, g_bars);

    static int smem_set = 0;
    if (!smem_set) {
        cudaFuncSetAttribute(mma_gemm<false>, cudaFuncAttributeMaxDynamicSharedMemorySize, SMEM_BYTES);
        cudaFuncSetAttribute(mma_gemm<true>,  cudaFuncAttributeMaxDynamicSharedMemorySize, SMEM_BYTES);
        smem_set = 1;
    }

    deg_kernel<<<2, 256>>>(adj, pD);
    buildM_kernel<<<(NN_*NN_)/256, 256>>>(adj, pD, pM);
    zero_bars_kernel<<<1, 32>>>(pBars);

    const long sX = (long)NN_*HH;
    const int  BT = BB*TT;

    // ---- GCN layer 1 ----
    mma_gemm<false><<<dim3(HH/BN, NN_/BM, BT), GTHR, SMEM_BYTES>>>(x, W1, nullptr, pHw,
        NN_, HH, CC, sX, BT, (long)CC*HH, TT, 0, 1, sX, 1, 0);
    mma_gemm<false><<<dim3(HH/BN, NN_/BM, BT), GTHR, SMEM_BYTES>>>(pM, pHw, b1, pTmp,
        NN_, HH, NN_, 0, 1, sX, BT, HH, TT, sX, 1, 0);
    graphnorm_kernel<<<(int)(TNH/256), 256>>>(pTmp, x, gn1w, gn1b, gn1m, pH1);

    // ---- GCN layer 2 ----
    mma_gemm<false><<<dim3(HH/BN, NN_/BM, BT), GTHR, SMEM_BYTES>>>(pH1, W2, nullptr, pHw,
        NN_, HH, HH, sX, BT, (long)HH*HH, TT, 0, 1, sX, 1, 0);
    mma_gemm<false><<<dim3(HH/BN, NN_/BM, BT), GTHR, SMEM_BYTES>>>(pM, pHw, b2, pTmp,
        NN_, HH, NN_, 0, 1, sX, BT, HH, TT, sX, 1, 0);
    graphnorm_kernel<<<(int)(TNH/256), 256>>>(pTmp, pH1, gn2w, gn2b, gn2m, pH2);

    // ---- LSTM layer 0: big input GEMM (split-K=8), reduce, persistent recurrence ----
    const long zTot = (long)BT*G4;      // 1,048,576
    mma_gemm<true><<<dim3(G4/BN, BT/BM, SPLITK0), GTHR, SMEM_BYTES>>>(pH2, Wih0, nullptr, pHw,
        BT, G4, DD, 0, 1, 0, 1, 0, 1, 0, SPLITK0, zTot);
    reduce_bias_kernel<<<(int)(zTot/256), 256>>>(pHw, bih0, pZ0, zTot, zTot, SPLITK0);
    lstm_persistent<true><<<LBLK, LTHR>>>(pZ0, Whh0, bhh0, pHA0, pHB0, pY0, pBars + 0);

    // ---- LSTM layer 1: input GEMM (split-K=4 into g_tmp), reduce, recurrence ----
    mma_gemm<true><<<dim3(G4/BN, BT/BM, SPLITK1), GTHR, SMEM_BYTES>>>(pY0, Wih1, nullptr, pTmp,
        BT, G4, HLL, 0, 1, 0, 1, 0, 1, 0, SPLITK1, zTot);
    reduce_bias_kernel<<<(int)(zTot/256), 256>>>(pTmp, bih1, pZ1, zTot, zTot, SPLITK1);
    lstm_persistent<false><<<LBLK, LTHR>>>(pZ1, Whh1, bhh1, pHA1, pHB1, nullptr, pBars + 1);

    // ---- projection ----
    proj_kernel<<<1, 128>>>(pHA1, Wp, bp, out);
}

// round 6
// speedup vs baseline: 1.5541x; 1.0398x over previous
#include <cuda_runtime.h>
#include <math.h>
#include <stdint.h>

// ---------------- problem constants ----------------
#define BB   16
#define TT   32
#define NN_  512
#define CC   128
#define HH   128
#define HLL  512
#define G4   (4*HLL)        // 2048
#define DD   (NN_*HH)       // 65536
#define TNH  ((long)TT*NN_*HH)   // 2,097,152
#define EPSN 1e-5f
#define SPLITK0 8
#define SPLITK1 4
#define LBLK 128
#define LTHR 256

// ---------------- device scratch ----------------
__device__ float g_d[NN_];
__device__ float g_M[NN_*NN_];
__device__ float g_hw [BB*TT*NN_*HH];      // also split-K partial buffer (Z0)
__device__ float g_tmp[BB*TT*NN_*HH];      // also split-K partial buffer (Z1)
__device__ float g_h1 [BB*TT*NN_*HH];
__device__ float g_h2 [BB*TT*NN_*HH];
__device__ float g_Z0[(long)BB*TT*G4];
__device__ float g_Z1[(long)BB*TT*G4];
__device__ float g_y0[(long)BB*TT*HLL];
__device__ float g_hA0[BB*HLL], g_hB0[BB*HLL];
__device__ float g_hA1[BB*HLL], g_hB1[BB*HLL];
__device__ unsigned g_bars[2];

// ---------------- helpers ----------------
__device__ __forceinline__ float sigf(float x) { return 1.0f/(1.0f+expf(-x)); }
__device__ __forceinline__ uint32_t f2tf32(float f) {
    uint32_t u;
    asm("cvt.rna.tf32.f32 %0, %1;" : "=r"(u) : "f"(f));
    return u;
}
__device__ __forceinline__ uint32_t cvt_raw(uint32_t raw) {
    return f2tf32(__uint_as_float(raw));
}
__device__ __forceinline__ void cp16(uint32_t saddr, const void* g) {
    asm volatile("cp.async.cg.shared.global [%0], [%1], 16;" :: "r"(saddr), "l"(g));
}
__device__ __forceinline__ void stcg(float* p, float v) {
    asm volatile("st.global.cg.f32 [%0], %1;" :: "l"(p), "f"(v));
}
__device__ __forceinline__ float ldcg(const float* p) {
    float v; asm volatile("ld.global.cg.f32 %0, [%1];" : "=f"(v) : "l"(p)); return v;
}
__device__ __forceinline__ void red_release(unsigned* p) {
    asm volatile("red.release.gpu.global.add.u32 [%0], 1;" :: "l"(p));
}
__device__ __forceinline__ unsigned ld_acquire(const unsigned* p) {
    unsigned v; asm volatile("ld.acquire.gpu.global.u32 %0, [%1];" : "=r"(v) : "l"(p)); return v;
}

// ---------------- graph normalization matrix ----------------
__global__ void deg_kernel(const float* __restrict__ adj, float* __restrict__ d) {
    int i = blockIdx.x*blockDim.x + threadIdx.x;
    if (i < NN_) {
        float s = 1.0f;
        for (int j = 0; j < NN_; j++) s += adj[(long)j*NN_ + i];
        d[i] = rsqrtf(s);
    }
}
__global__ void buildM_kernel(const float* __restrict__ adj, const float* __restrict__ d,
                              float* __restrict__ M) {
    int idx = blockIdx.x*blockDim.x + threadIdx.x;
    if (idx < NN_*NN_) {
        int j = idx >> 9, i = idx & (NN_-1);
        float a = adj[idx] + (i == j ? 1.0f : 0.0f);
        M[idx] = d[j]*a*d[i];
    }
}

// ============================================================================
// TF32 tensor-core GEMM. CTA tile 256x128x16, 16 warps of 64x32, 512 threads.
// 4-stage cp.async pipeline; fp32 in smem, cvt to tf32 at fragment load.
// Row-major padded smem: A[m][20], B-BT[n][20], B-NN[k][136]. Conflict-free.
// ============================================================================
#define BM 256
#define BN 128
#define BK 16
#define KP 20
#define BSN 136
#define GTHR 512
#define STAGES 4
#define STG_A (BM*KP)                 // 5120 words
#define STG_B 2560                    // max(BN*KP=2560, BK*BSN=2176)
#define STG_WORDS (STG_A + STG_B)     // 7680
#define SMEM_BYTES (STAGES*STG_WORDS*4)   // 122880

extern __shared__ uint32_t smem_dyn[];

template<bool BT_>
__global__ void __launch_bounds__(GTHR, 1)
mma_gemm(const float* __restrict__ Ab, const float* __restrict__ Bb,
         const float* __restrict__ biasb, float* __restrict__ Cb,
         int M, int N, int K,
         long sA, int modA, long sB, int modB,
         long sBias, int modBias, long sC,
         int splitK, long sSplit)
{
    int z = blockIdx.z;
    int batch = z / splitK, split = z - batch*splitK;
    const float* A = Ab + (long)(batch % modA) * sA;
    const float* B = Bb + (long)(batch % modB) * sB;
    float* C = Cb + (long)batch * sC + (long)split * sSplit;
    const float* bias = biasb ? biasb + (long)(batch % modBias) * sBias : nullptr;

    int kchunk = K / splitK;
    int kbeg = split * kchunk;
    int nk = kchunk / BK;

    uint32_t smem_u32 = (uint32_t)__cvta_generic_to_shared(smem_dyn);

    int tid = threadIdx.x;
    int lane = tid & 31;
    int warp = tid >> 5;
    int wm = (warp & 3) * 64;
    int wn = (warp >> 2) * 32;
    int m0 = blockIdx.y * BM;
    int n0 = blockIdx.x * BN;

    float acc[4][4][4];
    #pragma unroll
    for (int i = 0; i < 4; i++)
        #pragma unroll
        for (int j = 0; j < 4; j++)
            #pragma unroll
            for (int k = 0; k < 4; k++) acc[i][j][k] = 0.0f;

    // A loader: 1024 16B-chunks, 2/thread
    int a_m[2], a_kq[2];
    #pragma unroll
    for (int i = 0; i < 2; i++) { int idx = tid + i*GTHR; a_m[i] = idx >> 2; a_kq[i] = idx & 3; }
    // B loader: 512 chunks, 1/thread
    int b_i0, b_i1;
    if (BT_) { b_i0 = tid >> 2; b_i1 = tid & 3; }   // n, kq
    else     { b_i0 = tid >> 5; b_i1 = tid & 31; }  // r(k), cq

    auto issue = [&](int s, int kt) {
        int kg = kbeg + kt*BK;
        uint32_t base = smem_u32 + (uint32_t)(s*STG_WORDS)*4u;
        #pragma unroll
        for (int i = 0; i < 2; i++)
            cp16(base + (uint32_t)(a_m[i]*KP + a_kq[i]*4)*4u,
                 &A[(long)(m0 + a_m[i])*K + kg + a_kq[i]*4]);
        if (BT_)
            cp16(base + (uint32_t)(STG_A + b_i0*KP + b_i1*4)*4u,
                 &B[(long)(n0 + b_i0)*K + kg + b_i1*4]);
        else
            cp16(base + (uint32_t)(STG_A + b_i0*BSN + b_i1*4)*4u,
                 &B[(long)(kg + b_i0)*N + n0 + b_i1*4]);
    };

    #pragma unroll
    for (int s = 0; s < STAGES-1; s++) {
        issue(s, s);
        asm volatile("cp.async.commit_group;");
    }

    int lk = lane & 3, lg = lane >> 2;

    for (int kt = 0; kt < nk; kt++) {
        asm volatile("cp.async.wait_group %0;" :: "n"(STAGES-2));
        __syncthreads();

        int nxt = kt + STAGES - 1;
        if (nxt < nk) issue(nxt & (STAGES-1), nxt);
        asm volatile("cp.async.commit_group;");

        int cur = kt & (STAGES-1);
        const uint32_t* Asc = smem_dyn + cur*STG_WORDS;
        const uint32_t* Bsc = Asc + STG_A;

        #pragma unroll
        for (int ks = 0; ks < 2; ks++) {
            int kb = ks*8;
            uint32_t af[4][4];
            #pragma unroll
            for (int mt = 0; mt < 4; mt++) {
                int mr = wm + mt*16 + lg;
                af[mt][0] = cvt_raw(Asc[mr*KP + kb + lk]);
                af[mt][1] = cvt_raw(Asc[(mr+8)*KP + kb + lk]);
                af[mt][2] = cvt_raw(Asc[mr*KP + kb + lk + 4]);
                af[mt][3] = cvt_raw(Asc[(mr+8)*KP + kb + lk + 4]);
            }
            uint32_t bf[4][2];
            #pragma unroll
            for (int nt = 0; nt < 4; nt++) {
                int nb = wn + nt*8;
                if (BT_) {
                    bf[nt][0] = cvt_raw(Bsc[(nb+lg)*KP + kb + lk]);
                    bf[nt][1] = cvt_raw(Bsc[(nb+lg)*KP + kb + lk + 4]);
                } else {
                    bf[nt][0] = cvt_raw(Bsc[(kb+lk)*BSN + nb + lg]);
                    bf[nt][1] = cvt_raw(Bsc[(kb+lk+4)*BSN + nb + lg]);
                }
            }
            #pragma unroll
            for (int mt = 0; mt < 4; mt++)
                #pragma unroll
                for (int nt = 0; nt < 4; nt++) {
                    asm volatile(
                        "mma.sync.aligned.m16n8k8.row.col.f32.tf32.tf32.f32 "
                        "{%0,%1,%2,%3}, {%4,%5,%6,%7}, {%8,%9}, {%0,%1,%2,%3};"
                        : "+f"(acc[mt][nt][0]), "+f"(acc[mt][nt][1]),
                          "+f"(acc[mt][nt][2]), "+f"(acc[mt][nt][3])
                        : "r"(af[mt][0]), "r"(af[mt][1]), "r"(af[mt][2]), "r"(af[mt][3]),
                          "r"(bf[nt][0]), "r"(bf[nt][1]));
                }
        }
    }

    #pragma unroll
    for (int nt = 0; nt < 4; nt++) {
        int c0 = n0 + wn + nt*8 + 2*lk;
        float bv0 = bias ? bias[c0] : 0.0f;
        float bv1 = bias ? bias[c0+1] : 0.0f;
        #pragma unroll
        for (int mt = 0; mt < 4; mt++) {
            int r = m0 + wm + mt*16 + lg;
            float2 v0 = make_float2(acc[mt][nt][0] + bv0, acc[mt][nt][1] + bv1);
            float2 v1 = make_float2(acc[mt][nt][2] + bv0, acc[mt][nt][3] + bv1);
            *(float2*)&C[(long)r*N + c0] = v0;
            *(float2*)&C[(long)(r+8)*N + c0] = v1;
        }
    }
}

// ---------------- split-K reduce + bias ----------------
__global__ void reduce_bias_kernel(const float* __restrict__ P, const float* __restrict__ bias,
                                   float* __restrict__ Z, long total, long stride, int splits)
{
    long idx = (long)blockIdx.x*blockDim.x + threadIdx.x;
    if (idx >= total) return;
    float s = bias[idx & (G4-1)];
    #pragma unroll 8
    for (int i = 0; i < splits; i++) s += P[(long)i*stride + idx];
    Z[idx] = s;
}

// ---------------- GraphNorm + residual + ReLU ----------------
__global__ void graphnorm_kernel(const float* __restrict__ hraw, const float* __restrict__ res,
                                 const float* __restrict__ w, const float* __restrict__ bias,
                                 const float* __restrict__ ms, float* __restrict__ out)
{
    long p = (long)blockIdx.x*blockDim.x + threadIdx.x;
    if (p >= TNH) return;
    int h = (int)(p & (HH-1));
    float v[BB];
    float mean = 0.0f;
    #pragma unroll
    for (int b = 0; b < BB; b++) { v[b] = hraw[(long)b*TNH + p]; mean += v[b]; }
    mean *= (1.0f/BB);
    float msv = ms[h], var = 0.0f;
    #pragma unroll
    for (int b = 0; b < BB; b++) { v[b] -= msv*mean; var += v[b]*v[b]; }
    var *= (1.0f/BB);
    float inv = rsqrtf(var + EPSN);
    float wv = w[h]*inv, bv = bias[h];
    #pragma unroll
    for (int b = 0; b < BB; b++) {
        float r = wv*v[b] + bv + res[(long)b*TNH + p];
        out[(long)b*TNH + p] = fmaxf(r, 0.0f);
    }
}

// ---------------- zero barrier counters ----------------
__global__ void zero_bars_kernel(unsigned* bars) {
    if (threadIdx.x < 2) bars[threadIdx.x] = 0u;
}

// ============================================================================
// Persistent LSTM layer. 128 blocks x 256 thr, weights in registers.
// Inter-block sync: st.cg / ld.cg (L2-only) + red.release / ld.acquire grid
// barrier -- NO membar.gl / CCTL.IVALL L1 flushes on the step path.
// ============================================================================
template<bool WRITE_Y>
__global__ void __launch_bounds__(LTHR, 1)
lstm_persistent(const float* __restrict__ Z,
                const float* __restrict__ Whh,
                const float* __restrict__ bhh,
                float* __restrict__ bufA, float* __restrict__ bufB,
                float* __restrict__ y,
                unsigned* __restrict__ bar)
{
    __shared__ float hs[HLL][BB];
    __shared__ float red[8*16*17];
    __shared__ float gsum[16*16];

    const int t = threadIdx.x;
    const int blk = blockIdx.x;
    const int c = t & 15, sub = t >> 4;
    const int warp = t >> 5;
    const int mh_local = c & 3, gate = c >> 2;
    const int m = gate*HLL + blk*4 + mh_local;

    float w[32];
    {
        const float* wr = Whh + (long)m*HLL + sub*32;
        #pragma unroll
        for (int j = 0; j < 32; j++) w[j] = wr[j];
    }

    const int ub = t & 15;
    const int uml = (t >> 4) & 3;
    const int umh = blk*4 + uml;
    float creg = 0.0f;
    float bi = 0.f, bf = 0.f, bg = 0.f, bo = 0.f;
    if (t < 64) {
        bi = bhh[0*HLL + umh]; bf = bhh[1*HLL + umh];
        bg = bhh[2*HLL + umh]; bo = bhh[3*HLL + umh];
    }

    for (int i = t; i < HLL*BB; i += LTHR) (&hs[0][0])[i] = 0.0f;
    __syncthreads();

    unsigned target = 0;

    for (int step = 0; step < TT; step++) {
        float zi = 0.f, zf = 0.f, zg = 0.f, zo = 0.f;
        if (t < 64) {
            long zb = ((long)ub*TT + step)*G4;
            zi = __ldcs(&Z[zb + 0*HLL + umh]); zf = __ldcs(&Z[zb + 1*HLL + umh]);
            zg = __ldcs(&Z[zb + 2*HLL + umh]); zo = __ldcs(&Z[zb + 3*HLL + umh]);
        }

        float acc[BB];
        #pragma unroll
        for (int b = 0; b < BB; b++) acc[b] = 0.0f;
        #pragma unroll
        for (int j = 0; j < 32; j++) {
            float wv = w[j];
            const float* hr = &hs[sub*32 + j][0];
            #pragma unroll
            for (int b = 0; b < BB; b += 4) {
                float4 h4 = *(const float4*)&hr[b];
                acc[b+0] += wv*h4.x; acc[b+1] += wv*h4.y;
                acc[b+2] += wv*h4.z; acc[b+3] += wv*h4.w;
            }
        }
        #pragma unroll
        for (int b = 0; b < BB; b++)
            acc[b] += __shfl_down_sync(0xffffffffu, acc[b], 16);
        if ((t & 31) < 16) {
            float* rp = &red[(warp*16 + c)*17];
            #pragma unroll
            for (int b = 0; b < BB; b++) rp[b] = acc[b];
        }
        __syncthreads();
        {
            int c2 = t & 15, b2 = t >> 4;
            float s = 0.0f;
            #pragma unroll
            for (int s2 = 0; s2 < 8; s2++) s += red[(s2*16 + c2)*17 + b2];
            gsum[c2*16 + b2] = s;
        }
        __syncthreads();

        if (t < 64) {
            float gi = sigf (zi + gsum[(0*4+uml)*16 + ub] + bi);
            float gf = sigf (zf + gsum[(1*4+uml)*16 + ub] + bf);
            float gg = tanhf(zg + gsum[(2*4+uml)*16 + ub] + bg);
            float go = sigf (zo + gsum[(3*4+uml)*16 + ub] + bo);
            creg = gf*creg + gi*gg;
            float hn = go*tanhf(creg);
            float* hout = ((step+1) & 1) ? bufB : bufA;
            stcg(&hout[ub*HLL + umh], hn);
            if (WRITE_Y) stcg(&y[((long)ub*TT + step)*HLL + umh], hn);
        }
        __syncthreads();

        // ---- grid barrier (release/acquire, no L1 flush) ----
        target += LBLK;
        if (t == 0) {
            red_release(bar);
            while (ld_acquire(bar) < target) { }
        }
        __syncthreads();

        // ---- reload h into smem for next step (L2-only loads) ----
        if (step + 1 < TT) {
            const float* hin = ((step+1) & 1) ? bufB : bufA;
            for (int i = t; i < BB*HLL; i += LTHR) {
                int b = i >> 9, j = i & (HLL-1);
                hs[j][b] = ldcg(&hin[i]);
            }
            __syncthreads();
        }
    }
}

// ---------------- final projection ----------------
__global__ void proj_kernel(const float* __restrict__ h, const float* __restrict__ Wp,
                            const float* __restrict__ bp, float* __restrict__ out)
{
    int tid = threadIdx.x;
    int b = tid >> 3, o = tid & 7;
    float s = bp[o];
    const float* wr = Wp + o*HLL;
    const float* hr = h  + b*HLL;
    for (int m = 0; m < HLL; m++) s += ldcg(&hr[m])*wr[m];
    out[b*8 + o] = s;
}

// ---------------- launch ----------------
extern "C" void kernel_launch(void* const* d_in, const int* in_sizes, int n_in,
                              void* d_out, int out_size)
{
    const float* x    = (const float*)d_in[0];
    const float* adj  = (const float*)d_in[1];
    const float* W1   = (const float*)d_in[2];
    const float* b1   = (const float*)d_in[3];
    const float* W2   = (const float*)d_in[4];
    const float* b2   = (const float*)d_in[5];
    const float* gn1w = (const float*)d_in[6];
    const float* gn1b = (const float*)d_in[7];
    const float* gn1m = (const float*)d_in[8];
    const float* gn2w = (const float*)d_in[9];
    const float* gn2b = (const float*)d_in[10];
    const float* gn2m = (const float*)d_in[11];
    const float* Wih0 = (const float*)d_in[12];
    const float* Whh0 = (const float*)d_in[13];
    const float* bih0 = (const float*)d_in[14];
    const float* bhh0 = (const float*)d_in[15];
    const float* Wih1 = (const float*)d_in[16];
    const float* Whh1 = (const float*)d_in[17];
    const float* bih1 = (const float*)d_in[18];
    const float* bhh1 = (const float*)d_in[19];
    const float* Wp   = (const float*)d_in[20];
    const float* bp   = (const float*)d_in[21];
    float* out = (float*)d_out;

    float *pM, *pD, *pHw, *pTmp, *pH1, *pH2, *pZ0, *pZ1, *pY0;
    float *pHA0, *pHB0, *pHA1, *pHB1;
    unsigned* pBars;
    cudaGetSymbolAddress((void**)&pD,   g_d);
    cudaGetSymbolAddress((void**)&pM,   g_M);
    cudaGetSymbolAddress((void**)&pHw,  g_hw);
    cudaGetSymbolAddress((void**)&pTmp, g_tmp);
    cudaGetSymbolAddress((void**)&pH1,  g_h1);
    cudaGetSymbolAddress((void**)&pH2,  g_h2);
    cudaGetSymbolAddress((void**)&pZ0,  g_Z0);
    cudaGetSymbolAddress((void**)&pZ1,  g_Z1);
    cudaGetSymbolAddress((void**)&pY0,  g_y0);
    cudaGetSymbolAddress((void**)&pHA0, g_hA0);
    cudaGetSymbolAddress((void**)&pHB0, g_hB0);
    cudaGetSymbolAddress((void**)&pHA1, g_hA1);
    cudaGetSymbolAddress((void**)&pHB1, g_hB1);
    cudaGetSymbolAddress((void**)&pBars, g_bars);

    cudaFuncSetAttribute(mma_gemm<false>, cudaFuncAttributeMaxDynamicSharedMemorySize, SMEM_BYTES);
    cudaFuncSetAttribute(mma_gemm<true>,  cudaFuncAttributeMaxDynamicSharedMemorySize, SMEM_BYTES);

    deg_kernel<<<2, 256>>>(adj, pD);
    buildM_kernel<<<(NN_*NN_)/256, 256>>>(adj, pD, pM);
    zero_bars_kernel<<<1, 32>>>(pBars);

    const long sX = (long)NN_*HH;
    const int  BT = BB*TT;

    // ---- GCN layer 1 ----
    mma_gemm<false><<<dim3(HH/BN, NN_/BM, BT), GTHR, SMEM_BYTES>>>(x, W1, nullptr, pHw,
        NN_, HH, CC, sX, BT, (long)CC*HH, TT, 0, 1, sX, 1, 0);
    mma_gemm<false><<<dim3(HH/BN, NN_/BM, BT), GTHR, SMEM_BYTES>>>(pM, pHw, b1, pTmp,
        NN_, HH, NN_, 0, 1, sX, BT, HH, TT, sX, 1, 0);
    graphnorm_kernel<<<(int)(TNH/256), 256>>>(pTmp, x, gn1w, gn1b, gn1m, pH1);

    // ---- GCN layer 2 ----
    mma_gemm<false><<<dim3(HH/BN, NN_/BM, BT), GTHR, SMEM_BYTES>>>(pH1, W2, nullptr, pHw,
        NN_, HH, HH, sX, BT, (long)HH*HH, TT, 0, 1, sX, 1, 0);
    mma_gemm<false><<<dim3(HH/BN, NN_/BM, BT), GTHR, SMEM_BYTES>>>(pM, pHw, b2, pTmp,
        NN_, HH, NN_, 0, 1, sX, BT, HH, TT, sX, 1, 0);
    graphnorm_kernel<<<(int)(TNH/256), 256>>>(pTmp, pH1, gn2w, gn2b, gn2m, pH2);

    // ---- LSTM layer 0: big input GEMM (split-K=8), reduce, persistent recurrence ----
    const long zTot = (long)BT*G4;      // 1,048,576
    mma_gemm<true><<<dim3(G4/BN, BT/BM, SPLITK0), GTHR, SMEM_BYTES>>>(pH2, Wih0, nullptr, pHw,
        BT, G4, DD, 0, 1, 0, 1, 0, 1, 0, SPLITK0, zTot);
    reduce_bias_kernel<<<(int)(zTot/256), 256>>>(pHw, bih0, pZ0, zTot, zTot, SPLITK0);
    lstm_persistent<true><<<LBLK, LTHR>>>(pZ0, Whh0, bhh0, pHA0, pHB0, pY0, pBars + 0);

    // ---- LSTM layer 1: input GEMM (split-K=4), reduce, recurrence ----
    mma_gemm<true><<<dim3(G4/BN, BT/BM, SPLITK1), GTHR, SMEM_BYTES>>>(pY0, Wih1, nullptr, pTmp,
        BT, G4, HLL, 0, 1, 0, 1, 0, 1, 0, SPLITK1, zTot);
    reduce_bias_kernel<<<(int)(zTot/256), 256>>>(pTmp, bih1, pZ1, zTot, zTot, SPLITK1);
    lstm_persistent<false><<<LBLK, LTHR>>>(pZ1, Whh1, bhh1, pHA1, pHB1, nullptr, pBars + 1);

    // ---- projection ----
    proj_kernel<<<1, 128>>>(pHA1, Wp, bp, out);
}

// round 7
// speedup vs baseline: 1.7457x; 1.1233x over previous
#include <cuda_runtime.h>
#include <math.h>
#include <stdint.h>

// ---------------- problem constants ----------------
#define BB   16
#define TT   32
#define NN_  512
#define CC   128
#define HH   128
#define HLL  512
#define G4   (4*HLL)        // 2048
#define DD   (NN_*HH)       // 65536
#define TNH  ((long)TT*NN_*HH)   // 2,097,152
#define EPSN 1e-5f
#define SPLITK0 8
#define SPLITK1 4
#define LBLK 128
#define LTHR 256

// ---------------- device scratch ----------------
__device__ float g_d[NN_];
__device__ float g_M[NN_*NN_];
__device__ float g_hw [BB*TT*NN_*HH];      // also split-K partial buffer (Z0)
__device__ float g_tmp[BB*TT*NN_*HH];      // also split-K partial buffer (Z1)
__device__ float g_h1 [BB*TT*NN_*HH];
__device__ float g_h2 [BB*TT*NN_*HH];
__device__ float g_Z0[(long)BB*TT*G4];
__device__ float g_Z1[(long)BB*TT*G4];
__device__ float g_y0[(long)BB*TT*HLL];
__device__ float g_hA0[BB*HLL], g_hB0[BB*HLL];   // layout [HLL][BB]
__device__ float g_hA1[BB*HLL], g_hB1[BB*HLL];
__device__ unsigned g_bars[2];

// ---------------- helpers ----------------
__device__ __forceinline__ float sigf(float x) { return 1.0f/(1.0f+expf(-x)); }
__device__ __forceinline__ uint32_t f2tf32(float f) {
    uint32_t u;
    asm("cvt.rna.tf32.f32 %0, %1;" : "=r"(u) : "f"(f));
    return u;
}
__device__ __forceinline__ uint32_t cvt_raw(uint32_t raw) {
    return f2tf32(__uint_as_float(raw));
}
__device__ __forceinline__ void cp16(uint32_t saddr, const void* g) {
    asm volatile("cp.async.cg.shared.global [%0], [%1], 16;" :: "r"(saddr), "l"(g));
}
__device__ __forceinline__ void stcg(float* p, float v) {
    asm volatile("st.global.cg.f32 [%0], %1;" :: "l"(p), "f"(v));
}
__device__ __forceinline__ float ldcg(const float* p) {
    float v; asm volatile("ld.global.cg.f32 %0, [%1];" : "=f"(v) : "l"(p)); return v;
}
__device__ __forceinline__ float4 ldcg4(const float4* p) {
    float4 v;
    asm volatile("ld.global.cg.v4.f32 {%0,%1,%2,%3}, [%4];"
                 : "=f"(v.x), "=f"(v.y), "=f"(v.z), "=f"(v.w) : "l"(p));
    return v;
}
__device__ __forceinline__ unsigned ldcg_u32(const unsigned* p) {
    unsigned v; asm volatile("ld.global.cg.u32 %0, [%1];" : "=r"(v) : "l"(p)); return v;
}

// ---------------- graph normalization matrix ----------------
__global__ void deg_kernel(const float* __restrict__ adj, float* __restrict__ d) {
    int i = blockIdx.x*blockDim.x + threadIdx.x;
    if (i < NN_) {
        float s = 1.0f;
        for (int j = 0; j < NN_; j++) s += adj[(long)j*NN_ + i];
        d[i] = rsqrtf(s);
    }
}
__global__ void buildM_kernel(const float* __restrict__ adj, const float* __restrict__ d,
                              float* __restrict__ M) {
    int idx = blockIdx.x*blockDim.x + threadIdx.x;
    if (idx < NN_*NN_) {
        int j = idx >> 9, i = idx & (NN_-1);
        float a = adj[idx] + (i == j ? 1.0f : 0.0f);
        M[idx] = d[j]*a*d[i];
    }
}

// ============================================================================
// TF32 tensor-core GEMM. CTA tile 256x128x16, 8 warps of 64x64, 256 threads.
// 4-stage cp.async pipeline; fp32 in smem, cvt->tf32 at fragment load.
// Row-major padded smem: A[m][20], B-BT[n][20], B-NN[k][136]. Conflict-free.
// ============================================================================
#define BM 256
#define BN 128
#define BK 16
#define KP 20
#define BSN 136
#define GTHR 256
#define STAGES 4
#define STG_A (BM*KP)                 // 5120 words
#define STG_B 2560                    // max(BN*KP=2560, BK*BSN=2176)
#define STG_WORDS (STG_A + STG_B)     // 7680
#define SMEM_BYTES (STAGES*STG_WORDS*4)   // 122880

extern __shared__ uint32_t smem_dyn[];

template<bool BT_>
__global__ void __launch_bounds__(GTHR, 1)
mma_gemm(const float* __restrict__ Ab, const float* __restrict__ Bb,
         const float* __restrict__ biasb, float* __restrict__ Cb,
         int M, int N, int K,
         long sA, int modA, long sB, int modB,
         long sBias, int modBias, long sC,
         int splitK, long sSplit)
{
    int z = blockIdx.z;
    int batch = z / splitK, split = z - batch*splitK;
    const float* A = Ab + (long)(batch % modA) * sA;
    const float* B = Bb + (long)(batch % modB) * sB;
    float* C = Cb + (long)batch * sC + (long)split * sSplit;
    const float* bias = biasb ? biasb + (long)(batch % modBias) * sBias : nullptr;

    int kchunk = K / splitK;
    int kbeg = split * kchunk;
    int nk = kchunk / BK;

    uint32_t smem_u32 = (uint32_t)__cvta_generic_to_shared(smem_dyn);

    int tid = threadIdx.x;
    int lane = tid & 31;
    int warp = tid >> 5;
    int wm = (warp & 3) * 64;       // 4 m-subtiles
    int wn = (warp >> 2) * 64;      // 2 n-subtiles
    int m0 = blockIdx.y * BM;
    int n0 = blockIdx.x * BN;

    float acc[4][8][4];
    #pragma unroll
    for (int i = 0; i < 4; i++)
        #pragma unroll
        for (int j = 0; j < 8; j++)
            #pragma unroll
            for (int k = 0; k < 4; k++) acc[i][j][k] = 0.0f;

    // A loader: 1024 16B-chunks, 4/thread
    int a_m[4], a_kq[4];
    #pragma unroll
    for (int i = 0; i < 4; i++) { int idx = tid + i*GTHR; a_m[i] = idx >> 2; a_kq[i] = idx & 3; }
    // B loader: 512 chunks, 2/thread
    int b_i0[2], b_i1[2];
    #pragma unroll
    for (int i = 0; i < 2; i++) {
        int idx = tid + i*GTHR;
        if (BT_) { b_i0[i] = idx >> 2; b_i1[i] = idx & 3; }   // n, kq
        else     { b_i0[i] = idx >> 5; b_i1[i] = idx & 31; }  // r(k), cq
    }

    auto issue = [&](int s, int kt) {
        int kg = kbeg + kt*BK;
        uint32_t base = smem_u32 + (uint32_t)(s*STG_WORDS)*4u;
        #pragma unroll
        for (int i = 0; i < 4; i++)
            cp16(base + (uint32_t)(a_m[i]*KP + a_kq[i]*4)*4u,
                 &A[(long)(m0 + a_m[i])*K + kg + a_kq[i]*4]);
        #pragma unroll
        for (int i = 0; i < 2; i++) {
            if (BT_)
                cp16(base + (uint32_t)(STG_A + b_i0[i]*KP + b_i1[i]*4)*4u,
                     &B[(long)(n0 + b_i0[i])*K + kg + b_i1[i]*4]);
            else
                cp16(base + (uint32_t)(STG_A + b_i0[i]*BSN + b_i1[i]*4)*4u,
                     &B[(long)(kg + b_i0[i])*N + n0 + b_i1[i]*4]);
        }
    };

    #pragma unroll
    for (int s = 0; s < STAGES-1; s++) {
        issue(s, s);
        asm volatile("cp.async.commit_group;");
    }

    int lk = lane & 3, lg = lane >> 2;

    for (int kt = 0; kt < nk; kt++) {
        asm volatile("cp.async.wait_group %0;" :: "n"(STAGES-2));
        __syncthreads();

        int nxt = kt + STAGES - 1;
        if (nxt < nk) issue(nxt & (STAGES-1), nxt);
        asm volatile("cp.async.commit_group;");

        int cur = kt & (STAGES-1);
        const uint32_t* Asc = smem_dyn + cur*STG_WORDS;
        const uint32_t* Bsc = Asc + STG_A;

        #pragma unroll
        for (int ks = 0; ks < 2; ks++) {
            int kb = ks*8;
            uint32_t af[4][4];
            #pragma unroll
            for (int mt = 0; mt < 4; mt++) {
                int mr = wm + mt*16 + lg;
                af[mt][0] = cvt_raw(Asc[mr*KP + kb + lk]);
                af[mt][1] = cvt_raw(Asc[(mr+8)*KP + kb + lk]);
                af[mt][2] = cvt_raw(Asc[mr*KP + kb + lk + 4]);
                af[mt][3] = cvt_raw(Asc[(mr+8)*KP + kb + lk + 4]);
            }
            uint32_t bf[8][2];
            #pragma unroll
            for (int nt = 0; nt < 8; nt++) {
                int nb = wn + nt*8;
                if (BT_) {
                    bf[nt][0] = cvt_raw(Bsc[(nb+lg)*KP + kb + lk]);
                    bf[nt][1] = cvt_raw(Bsc[(nb+lg)*KP + kb + lk + 4]);
                } else {
                    bf[nt][0] = cvt_raw(Bsc[(kb+lk)*BSN + nb + lg]);
                    bf[nt][1] = cvt_raw(Bsc[(kb+lk+4)*BSN + nb + lg]);
                }
            }
            #pragma unroll
            for (int mt = 0; mt < 4; mt++)
                #pragma unroll
                for (int nt = 0; nt < 8; nt++) {
                    asm volatile(
                        "mma.sync.aligned.m16n8k8.row.col.f32.tf32.tf32.f32 "
                        "{%0,%1,%2,%3}, {%4,%5,%6,%7}, {%8,%9}, {%0,%1,%2,%3};"
                        : "+f"(acc[mt][nt][0]), "+f"(acc[mt][nt][1]),
                          "+f"(acc[mt][nt][2]), "+f"(acc[mt][nt][3])
                        : "r"(af[mt][0]), "r"(af[mt][1]), "r"(af[mt][2]), "r"(af[mt][3]),
                          "r"(bf[nt][0]), "r"(bf[nt][1]));
                }
        }
    }

    #pragma unroll
    for (int nt = 0; nt < 8; nt++) {
        int c0 = n0 + wn + nt*8 + 2*lk;
        float bv0 = bias ? bias[c0] : 0.0f;
        float bv1 = bias ? bias[c0+1] : 0.0f;
        #pragma unroll
        for (int mt = 0; mt < 4; mt++) {
            int r = m0 + wm + mt*16 + lg;
            float2 v0 = make_float2(acc[mt][nt][0] + bv0, acc[mt][nt][1] + bv1);
            float2 v1 = make_float2(acc[mt][nt][2] + bv0, acc[mt][nt][3] + bv1);
            *(float2*)&C[(long)r*N + c0] = v0;
            *(float2*)&C[(long)(r+8)*N + c0] = v1;
        }
    }
}

// ---------------- split-K reduce + bias ----------------
__global__ void reduce_bias_kernel(const float* __restrict__ P, const float* __restrict__ bias,
                                   float* __restrict__ Z, long total, long stride, int splits)
{
    long idx = (long)blockIdx.x*blockDim.x + threadIdx.x;
    if (idx >= total) return;
    float s = bias[idx & (G4-1)];
    #pragma unroll 8
    for (int i = 0; i < splits; i++) s += P[(long)i*stride + idx];
    Z[idx] = s;
}

// ---------------- GraphNorm + residual + ReLU ----------------
__global__ void graphnorm_kernel(const float* __restrict__ hraw, const float* __restrict__ res,
                                 const float* __restrict__ w, const float* __restrict__ bias,
                                 const float* __restrict__ ms, float* __restrict__ out)
{
    long p = (long)blockIdx.x*blockDim.x + threadIdx.x;
    if (p >= TNH) return;
    int h = (int)(p & (HH-1));
    float v[BB];
    float mean = 0.0f;
    #pragma unroll
    for (int b = 0; b < BB; b++) { v[b] = hraw[(long)b*TNH + p]; mean += v[b]; }
    mean *= (1.0f/BB);
    float msv = ms[h], var = 0.0f;
    #pragma unroll
    for (int b = 0; b < BB; b++) { v[b] -= msv*mean; var += v[b]*v[b]; }
    var *= (1.0f/BB);
    float inv = rsqrtf(var + EPSN);
    float wv = w[h]*inv, bv = bias[h];
    #pragma unroll
    for (int b = 0; b < BB; b++) {
        float r = wv*v[b] + bv + res[(long)b*TNH + p];
        out[(long)b*TNH + p] = fmaxf(r, 0.0f);
    }
}

// ---------------- zero barrier counters ----------------
__global__ void zero_bars_kernel(unsigned* bars) {
    if (threadIdx.x < 2) bars[threadIdx.x] = 0u;
}

// ============================================================================
// Persistent LSTM layer. 128 blocks x 256 thr, weights in registers.
// h buffers in [HLL][BB] layout (vectorized reload). Barrier: writer-side
// membar.gl (once/step) + red.relaxed + relaxed ld.cg polling (no CCTL in loop).
// ============================================================================
template<bool WRITE_Y>
__global__ void __launch_bounds__(LTHR, 1)
lstm_persistent(const float* __restrict__ Z,
                const float* __restrict__ Whh,
                const float* __restrict__ bhh,
                float* __restrict__ bufA, float* __restrict__ bufB,  // [HLL][BB]
                float* __restrict__ y,
                unsigned* __restrict__ bar)
{
    __shared__ float hs[HLL][BB];
    __shared__ float red[8*16*17];
    __shared__ float gsum[16*16];

    const int t = threadIdx.x;
    const int blk = blockIdx.x;
    const int c = t & 15, sub = t >> 4;
    const int warp = t >> 5;
    const int mh_local = c & 3, gate = c >> 2;
    const int m = gate*HLL + blk*4 + mh_local;

    float w[32];
    {
        const float* wr = Whh + (long)m*HLL + sub*32;
        #pragma unroll
        for (int j = 0; j < 32; j++) w[j] = wr[j];
    }

    const int ub = t & 15;
    const int uml = (t >> 4) & 3;
    const int umh = blk*4 + uml;
    float creg = 0.0f;
    float bi = 0.f, bf = 0.f, bg = 0.f, bo = 0.f;
    if (t < 64) {
        bi = bhh[0*HLL + umh]; bf = bhh[1*HLL + umh];
        bg = bhh[2*HLL + umh]; bo = bhh[3*HLL + umh];
    }

    for (int i = t; i < HLL*BB; i += LTHR) (&hs[0][0])[i] = 0.0f;
    __syncthreads();

    unsigned target = 0;

    for (int step = 0; step < TT; step++) {
        float zi = 0.f, zf = 0.f, zg = 0.f, zo = 0.f;
        if (t < 64) {
            long zb = ((long)ub*TT + step)*G4;
            zi = __ldcs(&Z[zb + 0*HLL + umh]); zf = __ldcs(&Z[zb + 1*HLL + umh]);
            zg = __ldcs(&Z[zb + 2*HLL + umh]); zo = __ldcs(&Z[zb + 3*HLL + umh]);
        }

        float acc[BB];
        #pragma unroll
        for (int b = 0; b < BB; b++) acc[b] = 0.0f;
        #pragma unroll
        for (int j = 0; j < 32; j++) {
            float wv = w[j];
            const float* hr = &hs[sub*32 + j][0];
            #pragma unroll
            for (int b = 0; b < BB; b += 4) {
                float4 h4 = *(const float4*)&hr[b];
                acc[b+0] += wv*h4.x; acc[b+1] += wv*h4.y;
                acc[b+2] += wv*h4.z; acc[b+3] += wv*h4.w;
            }
        }
        #pragma unroll
        for (int b = 0; b < BB; b++)
            acc[b] += __shfl_down_sync(0xffffffffu, acc[b], 16);
        if ((t & 31) < 16) {
            float* rp = &red[(warp*16 + c)*17];
            #pragma unroll
            for (int b = 0; b < BB; b++) rp[b] = acc[b];
        }
        __syncthreads();
        {
            int c2 = t & 15, b2 = t >> 4;
            float s = 0.0f;
            #pragma unroll
            for (int s2 = 0; s2 < 8; s2++) s += red[(s2*16 + c2)*17 + b2];
            gsum[c2*16 + b2] = s;
        }
        __syncthreads();

        if (t < 64) {
            float gi = sigf (zi + gsum[(0*4+uml)*16 + ub] + bi);
            float gf = sigf (zf + gsum[(1*4+uml)*16 + ub] + bf);
            float gg = tanhf(zg + gsum[(2*4+uml)*16 + ub] + bg);
            float go = sigf (zo + gsum[(3*4+uml)*16 + ub] + bo);
            creg = gf*creg + gi*gg;
            float hn = go*tanhf(creg);
            float* hout = ((step+1) & 1) ? bufB : bufA;
            stcg(&hout[umh*BB + ub], hn);                        // [j][b] layout
            if (WRITE_Y) stcg(&y[((long)ub*TT + step)*HLL + umh], hn);
            asm volatile("membar.gl;" ::: "memory");             // once per step
        }
        __syncthreads();

        // ---- grid barrier: relaxed red + relaxed L2 polling ----
        target += LBLK;
        if (t == 0) {
            asm volatile("red.relaxed.gpu.global.add.u32 [%0], 1;" :: "l"(bar));
            unsigned v;
            do { v = ldcg_u32(bar); } while (v < target);
        }
        __syncthreads();

        // ---- reload h into smem (vectorized, L2-only) ----
        if (step + 1 < TT) {
            const float4* hin = (const float4*)(((step+1) & 1) ? bufB : bufA);
            float4* hsd = (float4*)&hs[0][0];
            #pragma unroll
            for (int q = t; q < HLL*BB/4; q += LTHR)
                hsd[q] = ldcg4(&hin[q]);
            __syncthreads();
        }
    }
}

// ---------------- final projection (h in [j][b] layout) ----------------
__global__ void proj_kernel(const float* __restrict__ h, const float* __restrict__ Wp,
                            const float* __restrict__ bp, float* __restrict__ out)
{
    int tid = threadIdx.x;
    int b = tid >> 3, o = tid & 7;
    float s = bp[o];
    const float* wr = Wp + o*HLL;
    for (int m = 0; m < HLL; m++) s += ldcg(&h[m*BB + b])*wr[m];
    out[b*8 + o] = s;
}

// ---------------- launch ----------------
extern "C" void kernel_launch(void* const* d_in, const int* in_sizes, int n_in,
                              void* d_out, int out_size)
{
    const float* x    = (const float*)d_in[0];
    const float* adj  = (const float*)d_in[1];
    const float* W1   = (const float*)d_in[2];
    const float* b1   = (const float*)d_in[3];
    const float* W2   = (const float*)d_in[4];
    const float* b2   = (const float*)d_in[5];
    const float* gn1w = (const float*)d_in[6];
    const float* gn1b = (const float*)d_in[7];
    const float* gn1m = (const float*)d_in[8];
    const float* gn2w = (const float*)d_in[9];
    const float* gn2b = (const float*)d_in[10];
    const float* gn2m = (const float*)d_in[11];
    const float* Wih0 = (const float*)d_in[12];
    const float* Whh0 = (const float*)d_in[13];
    const float* bih0 = (const float*)d_in[14];
    const float* bhh0 = (const float*)d_in[15];
    const float* Wih1 = (const float*)d_in[16];
    const float* Whh1 = (const float*)d_in[17];
    const float* bih1 = (const float*)d_in[18];
    const float* bhh1 = (const float*)d_in[19];
    const float* Wp   = (const float*)d_in[20];
    const float* bp   = (const float*)d_in[21];
    float* out = (float*)d_out;

    float *pM, *pD, *pHw, *pTmp, *pH1, *pH2, *pZ0, *pZ1, *pY0;
    float *pHA0, *pHB0, *pHA1, *pHB1;
    unsigned* pBars;
    cudaGetSymbolAddress((void**)&pD,   g_d);
    cudaGetSymbolAddress((void**)&pM,   g_M);
    cudaGetSymbolAddress((void**)&pHw,  g_hw);
    cudaGetSymbolAddress((void**)&pTmp, g_tmp);
    cudaGetSymbolAddress((void**)&pH1,  g_h1);
    cudaGetSymbolAddress((void**)&pH2,  g_h2);
    cudaGetSymbolAddress((void**)&pZ0,  g_Z0);
    cudaGetSymbolAddress((void**)&pZ1,  g_Z1);
    cudaGetSymbolAddress((void**)&pY0,  g_y0);
    cudaGetSymbolAddress((void**)&pHA0, g_hA0);
    cudaGetSymbolAddress((void**)&pHB0, g_hB0);
    cudaGetSymbolAddress((void**)&pHA1, g_hA1);
    cudaGetSymbolAddress((void**)&pHB1, g_hB1);
    cudaGetSymbolAddress((void**)&pBars, g_bars);

    cudaFuncSetAttribute(mma_gemm<false>, cudaFuncAttributeMaxDynamicSharedMemorySize, SMEM_BYTES);
    cudaFuncSetAttribute(mma_gemm<true>,  cudaFuncAttributeMaxDynamicSharedMemorySize, SMEM_BYTES);

    deg_kernel<<<2, 256>>>(adj, pD);
    buildM_kernel<<<(NN_*NN_)/256, 256>>>(adj, pD, pM);
    zero_bars_kernel<<<1, 32>>>(pBars);

    const long sX = (long)NN_*HH;
    const int  BT = BB*TT;

    // ---- GCN layer 1 ----
    mma_gemm<false><<<dim3(HH/BN, NN_/BM, BT), GTHR, SMEM_BYTES>>>(x, W1, nullptr, pHw,
        NN_, HH, CC, sX, BT, (long)CC*HH, TT, 0, 1, sX, 1, 0);
    mma_gemm<false><<<dim3(HH/BN, NN_/BM, BT), GTHR, SMEM_BYTES>>>(pM, pHw, b1, pTmp,
        NN_, HH, NN_, 0, 1, sX, BT, HH, TT, sX, 1, 0);
    graphnorm_kernel<<<(int)(TNH/256), 256>>>(pTmp, x, gn1w, gn1b, gn1m, pH1);

    // ---- GCN layer 2 ----
    mma_gemm<false><<<dim3(HH/BN, NN_/BM, BT), GTHR, SMEM_BYTES>>>(pH1, W2, nullptr, pHw,
        NN_, HH, HH, sX, BT, (long)HH*HH, TT, 0, 1, sX, 1, 0);
    mma_gemm<false><<<dim3(HH/BN, NN_/BM, BT), GTHR, SMEM_BYTES>>>(pM, pHw, b2, pTmp,
        NN_, HH, NN_, 0, 1, sX, BT, HH, TT, sX, 1, 0);
    graphnorm_kernel<<<(int)(TNH/256), 256>>>(pTmp, pH1, gn2w, gn2b, gn2m, pH2);

    // ---- LSTM layer 0: big input GEMM (split-K=8), reduce, persistent recurrence ----
    const long zTot = (long)BT*G4;      // 1,048,576
    mma_gemm<true><<<dim3(G4/BN, BT/BM, SPLITK0), GTHR, SMEM_BYTES>>>(pH2, Wih0, nullptr, pHw,
        BT, G4, DD, 0, 1, 0, 1, 0, 1, 0, SPLITK0, zTot);
    reduce_bias_kernel<<<(int)(zTot/256), 256>>>(pHw, bih0, pZ0, zTot, zTot, SPLITK0);
    lstm_persistent<true><<<LBLK, LTHR>>>(pZ0, Whh0, bhh0, pHA0, pHB0, pY0, pBars + 0);

    // ---- LSTM layer 1: input GEMM (split-K=4), reduce, recurrence ----
    mma_gemm<true><<<dim3(G4/BN, BT/BM, SPLITK1), GTHR, SMEM_BYTES>>>(pY0, Wih1, nullptr, pTmp,
        BT, G4, HLL, 0, 1, 0, 1, 0, 1, 0, SPLITK1, zTot);
    reduce_bias_kernel<<<(int)(zTot/256), 256>>>(pTmp, bih1, pZ1, zTot, zTot, SPLITK1);
    lstm_persistent<false><<<LBLK, LTHR>>>(pZ1, Whh1, bhh1, pHA1, pHB1, nullptr, pBars + 1);

    // ---- projection ----
    proj_kernel<<<1, 128>>>(pHA1, Wp, bp, out);
}

// round 9
// speedup vs baseline: 2.9218x; 1.6737x over previous
#include <cuda_runtime.h>
#include <cuda_fp16.h>
#include <math.h>
#include <stdint.h>

// ---------------- problem constants ----------------
#define BB   16
#define TT   32
#define NN_  512
#define CC   128
#define HH   128
#define HLL  512
#define G4   2048
#define DD   65536
#define TNH  ((long)TT*NN_*HH)
#define EPSN 1e-5f
#define SPLITK0 8
#define SPLITK1 4
#define LBLK 128
#define LTHR 256

// ---------------- device scratch ----------------
__device__ float g_d[NN_];
__device__ float g_tmp[BB*TT*NN_*HH];            // GN inputs; then split-K partials
__device__ float g_h1 [BB*TT*NN_*HH];            // GN1 fp32 out (residual for GN2)
__device__ float g_Z0[(long)BB*TT*G4];
__device__ float g_Z1[(long)BB*TT*G4];
__device__ __align__(16) float g_hA0[BB*HLL], g_hB0[BB*HLL];   // [HLL][BB]
__device__ __align__(16) float g_hA1[BB*HLL], g_hB1[BB*HLL];
__device__ unsigned g_bars[2];

__device__ __half g_x16  [BB*TT*NN_*CC];
__device__ __half g_hw16 [BB*TT*NN_*HH];
__device__ __half g_h116 [BB*TT*NN_*HH];
__device__ __half g_h216 [BB*TT*NN_*HH];
__device__ __half g_W116 [TT*CC*HH];
__device__ __half g_W216 [TT*HH*HH];
__device__ __half g_Wih016[(long)G4*DD];
__device__ __half g_Wih116[G4*HLL];
__device__ __half g_M16  [NN_*NN_];
__device__ __half g_y016 [BB*TT*HLL];

// ---------------- helpers ----------------
__device__ __forceinline__ float sigf(float x) { return 1.0f/(1.0f+expf(-x)); }
__device__ __forceinline__ void cp16(uint32_t saddr, const void* g) {
    asm volatile("cp.async.cg.shared.global [%0], [%1], 16;" :: "r"(saddr), "l"(g));
}
__device__ __forceinline__ void stcg(float* p, float v) {
    asm volatile("st.global.cg.f32 [%0], %1;" :: "l"(p), "f"(v));
}
__device__ __forceinline__ float4 ldcg4(const float4* p) {
    float4 v;
    asm volatile("ld.global.cg.v4.f32 {%0,%1,%2,%3}, [%4];"
                 : "=f"(v.x), "=f"(v.y), "=f"(v.z), "=f"(v.w) : "l"(p));
    return v;
}
__device__ __forceinline__ void ldm_x4(uint32_t* r, uint32_t a) {
    asm volatile("ldmatrix.sync.aligned.m8n8.x4.shared.b16 {%0,%1,%2,%3}, [%4];"
                 : "=r"(r[0]), "=r"(r[1]), "=r"(r[2]), "=r"(r[3]) : "r"(a));
}
__device__ __forceinline__ void ldm_x4t(uint32_t* r, uint32_t a) {
    asm volatile("ldmatrix.sync.aligned.m8n8.x4.trans.shared.b16 {%0,%1,%2,%3}, [%4];"
                 : "=r"(r[0]), "=r"(r[1]), "=r"(r[2]), "=r"(r[3]) : "r"(a));
}
__device__ __forceinline__ void mma16816(float* d, const uint32_t* a, const uint32_t* b) {
    asm volatile("mma.sync.aligned.m16n8k16.row.col.f32.f16.f16.f32 "
                 "{%0,%1,%2,%3},{%4,%5,%6,%7},{%8,%9},{%0,%1,%2,%3};"
                 : "+f"(d[0]), "+f"(d[1]), "+f"(d[2]), "+f"(d[3])
                 : "r"(a[0]), "r"(a[1]), "r"(a[2]), "r"(a[3]), "r"(b[0]), "r"(b[1]));
}

// ---------------- fp32 -> fp16 ----------------
__global__ void f2h_kernel(const float* __restrict__ s, __half* __restrict__ d, long n) {
    long i = ((long)blockIdx.x*blockDim.x + threadIdx.x)*4;
    if (i < n) {
        float4 v = *(const float4*)&s[i];
        *(__half2*)&d[i]   = __floats2half2_rn(v.x, v.y);
        *(__half2*)&d[i+2] = __floats2half2_rn(v.z, v.w);
    }
}

// ---------------- graph normalization matrix ----------------
__global__ void deg_kernel(const float* __restrict__ adj, float* __restrict__ d) {
    int i = blockIdx.x*blockDim.x + threadIdx.x;
    if (i < NN_) {
        float s = 1.0f;
        for (int j = 0; j < NN_; j++) s += adj[(long)j*NN_ + i];
        d[i] = rsqrtf(s);
    }
}
__global__ void buildM_kernel(const float* __restrict__ adj, const float* __restrict__ d,
                              __half* __restrict__ M16) {
    int idx = blockIdx.x*blockDim.x + threadIdx.x;
    if (idx < NN_*NN_) {
        int j = idx >> 9, i = idx & (NN_-1);
        float a = adj[idx] + (i == j ? 1.0f : 0.0f);
        M16[idx] = __float2half(d[j]*a*d[i]);
    }
}

// ============================================================================
// FP16 GEMM: C = A @ B (+bias). A fp16 [m][k]. BNN=true: B fp16 [k][n];
// BNN=false: B fp16 [n][k] (B^T). CTA 128x128x64, 8 warps of 64x32,
// 3-stage cp.async, ldmatrix fragments, mma.m16n8k16, fp32 accum.
// Output: C16 (fp16) if non-null, else C32 (fp32, split-K partial capable).
// ============================================================================
#define HBM 128
#define HBN 128
#define HBK 64
#define HKP 72
#define HNP 136
#define HSA (HBM*HKP)         // 9216 halves
#define HSB 9216              // max(HBN*HKP, HBK*HNP=8704)
#define HSTG ((HSA+HSB)*2)    // 36864 bytes per stage
#define HSMEM (3*HSTG)        // 110592

extern __shared__ char hsm[];

template<bool BNN>
__global__ void __launch_bounds__(256, 2)
hgemm(const __half* __restrict__ Ab, const __half* __restrict__ Bb,
      const float* __restrict__ biasb, float* __restrict__ C32b, __half* __restrict__ C16b,
      int M, int N, int K,
      long sA, int modA, long sB, int modB, long sBias, int modBias,
      long sC, int splitK, long sSplit)
{
    int z = blockIdx.z;
    int batch = z / splitK, split = z - batch*splitK;
    const __half* A = Ab + (long)(batch % modA)*sA;
    const __half* B = Bb + (long)(batch % modB)*sB;
    const float* bias = biasb ? biasb + (long)(batch % modBias)*sBias : nullptr;
    float* C32 = C32b ? C32b + (long)batch*sC + (long)split*sSplit : nullptr;
    __half* C16 = C16b ? C16b + (long)batch*sC : nullptr;

    int kchunk = K/splitK, kbeg = split*kchunk, nk = kchunk/HBK;
    uint32_t sm = (uint32_t)__cvta_generic_to_shared(hsm);

    int tid = threadIdx.x, lane = tid & 31, warp = tid >> 5;
    int wm = (warp & 1)*64, wn = (warp >> 1)*32;
    int m0 = blockIdx.y*HBM, n0 = blockIdx.x*HBN;

    float acc[4][4][4];
    #pragma unroll
    for (int i = 0; i < 4; i++)
        #pragma unroll
        for (int j = 0; j < 4; j++)
            #pragma unroll
            for (int k = 0; k < 4; k++) acc[i][j][k] = 0.0f;

    // loader coords (4 x 16B chunks per thread for A and for B)
    int a_m[4], a_kc[4], b0i[4], b1i[4];
    #pragma unroll
    for (int i = 0; i < 4; i++) {
        int idx = tid + i*256;
        a_m[i] = idx >> 3; a_kc[i] = idx & 7;
        if (BNN) { b0i[i] = idx >> 4; b1i[i] = idx & 15; }   // k, nchunk
        else     { b0i[i] = idx >> 3; b1i[i] = idx & 7; }    // n, kchunk
    }

    auto issue = [&](int s, int kt) {
        int kg = kbeg + kt*HBK;
        uint32_t ba = sm + (uint32_t)s*HSTG;
        uint32_t bb = ba + HSA*2;
        #pragma unroll
        for (int i = 0; i < 4; i++)
            cp16(ba + (uint32_t)(a_m[i]*HKP + a_kc[i]*8)*2,
                 &A[(long)(m0 + a_m[i])*K + kg + a_kc[i]*8]);
        #pragma unroll
        for (int i = 0; i < 4; i++) {
            if (BNN)
                cp16(bb + (uint32_t)(b0i[i]*HNP + b1i[i]*8)*2,
                     &B[(long)(kg + b0i[i])*N + n0 + b1i[i]*8]);
            else
                cp16(bb + (uint32_t)(b0i[i]*HKP + b1i[i]*8)*2,
                     &B[(long)(n0 + b0i[i])*K + kg + b1i[i]*8]);
        }
    };

    issue(0, 0); asm volatile("cp.async.commit_group;");
    issue(1, 1); asm volatile("cp.async.commit_group;");

    // fragment smem offsets (bytes within stage)
    uint32_t aoff[4];
    #pragma unroll
    for (int mt = 0; mt < 4; mt++)
        aoff[mt] = (uint32_t)((wm + mt*16 + (lane & 15))*HKP + (lane >> 4)*8)*2;
    int quad = lane >> 3;
    uint32_t boff[2];
    #pragma unroll
    for (int p = 0; p < 2; p++) {
        if (BNN)
            boff[p] = (uint32_t)(((quad & 1)*8 + (lane & 7))*HNP
                      + wn + p*16 + (quad >> 1)*8)*2;
        else
            boff[p] = (uint32_t)((wn + p*16 + (quad >> 1)*8 + (lane & 7))*HKP
                      + (quad & 1)*8)*2;
    }

    for (int kt = 0; kt < nk; kt++) {
        asm volatile("cp.async.wait_group 1;");
        __syncthreads();
        if (kt + 2 < nk) issue((kt + 2) % 3, kt + 2);
        asm volatile("cp.async.commit_group;");

        uint32_t sa = sm + (uint32_t)(kt % 3)*HSTG;
        uint32_t sb = sa + HSA*2;

        #pragma unroll
        for (int ks = 0; ks < 4; ks++) {
            uint32_t af[4][4];
            #pragma unroll
            for (int mt = 0; mt < 4; mt++) ldm_x4(af[mt], sa + aoff[mt] + ks*32);
            uint32_t bf[4][2];
            #pragma unroll
            for (int p = 0; p < 2; p++) {
                uint32_t r[4];
                if (BNN) ldm_x4t(r, sb + boff[p] + (uint32_t)ks*16*HNP*2);
                else     ldm_x4 (r, sb + boff[p] + ks*32);
                bf[p*2][0] = r[0]; bf[p*2][1] = r[1];
                bf[p*2+1][0] = r[2]; bf[p*2+1][1] = r[3];
            }
            #pragma unroll
            for (int mt = 0; mt < 4; mt++)
                #pragma unroll
                for (int nt = 0; nt < 4; nt++)
                    mma16816(acc[mt][nt], af[mt], bf[nt]);
        }
    }

    #pragma unroll
    for (int nt = 0; nt < 4; nt++) {
        int c0 = n0 + wn + nt*8 + (lane & 3)*2;
        float bv0 = bias ? bias[c0] : 0.0f;
        float bv1 = bias ? bias[c0+1] : 0.0f;
        #pragma unroll
        for (int mt = 0; mt < 4; mt++) {
            int r = m0 + wm + mt*16 + (lane >> 2);
            float v00 = acc[mt][nt][0] + bv0, v01 = acc[mt][nt][1] + bv1;
            float v10 = acc[mt][nt][2] + bv0, v11 = acc[mt][nt][3] + bv1;
            if (C16) {
                *(__half2*)&C16[(long)r*N + c0]     = __floats2half2_rn(v00, v01);
                *(__half2*)&C16[(long)(r+8)*N + c0] = __floats2half2_rn(v10, v11);
            } else {
                *(float2*)&C32[(long)r*N + c0]     = make_float2(v00, v01);
                *(float2*)&C32[(long)(r+8)*N + c0] = make_float2(v10, v11);
            }
        }
    }
}

// ---------------- split-K reduce + bias ----------------
__global__ void reduce_bias_kernel(const float* __restrict__ P, const float* __restrict__ bias,
                                   float* __restrict__ Z, long total, long stride, int splits)
{
    long idx = (long)blockIdx.x*blockDim.x + threadIdx.x;
    if (idx >= total) return;
    float s = bias[idx & (G4-1)];
    #pragma unroll 8
    for (int i = 0; i < splits; i++) s += P[(long)i*stride + idx];
    Z[idx] = s;
}

// ---------------- GraphNorm + residual + ReLU (fp32 + fp16 out) ----------------
__global__ void graphnorm_kernel(const float* __restrict__ hraw, const float* __restrict__ res,
                                 const float* __restrict__ w, const float* __restrict__ bias,
                                 const float* __restrict__ ms,
                                 float* __restrict__ out32, __half* __restrict__ out16)
{
    long p = (long)blockIdx.x*blockDim.x + threadIdx.x;
    if (p >= TNH) return;
    int h = (int)(p & (HH-1));
    float v[BB];
    float mean = 0.0f;
    #pragma unroll
    for (int b = 0; b < BB; b++) { v[b] = hraw[(long)b*TNH + p]; mean += v[b]; }
    mean *= (1.0f/BB);
    float msv = ms[h], var = 0.0f;
    #pragma unroll
    for (int b = 0; b < BB; b++) { v[b] -= msv*mean; var += v[b]*v[b]; }
    var *= (1.0f/BB);
    float inv = rsqrtf(var + EPSN);
    float wv = w[h]*inv, bv = bias[h];
    #pragma unroll
    for (int b = 0; b < BB; b++) {
        float r = fmaxf(wv*v[b] + bv + res[(long)b*TNH + p], 0.0f);
        if (out32) out32[(long)b*TNH + p] = r;
        out16[(long)b*TNH + p] = __float2half(r);
    }
}

// ---------------- zero barrier counters ----------------
__global__ void zero_bars_kernel(unsigned* bars) {
    if (threadIdx.x < 2) bars[threadIdx.x] = 0u;
}

// ============================================================================
// Persistent LSTM. 128 blocks x 256 thr, Whh (fp32) in registers.
// Sync: st.cg stores -> __threadfence -> atomicAdd + volatile poll -> ld.cg.
// ============================================================================
template<bool WRITE_Y>
__global__ void __launch_bounds__(LTHR, 1)
lstm_persistent(const float* __restrict__ Z,
                const float* __restrict__ Whh,
                const float* __restrict__ bhh,
                float* __restrict__ bufA, float* __restrict__ bufB,  // [HLL][BB]
                __half* __restrict__ y16,
                unsigned* __restrict__ bar)
{
    __shared__ float hs[HLL][BB];
    __shared__ float red[8*16*17];
    __shared__ float gsum[16*16];

    const int t = threadIdx.x;
    const int blk = blockIdx.x;
    const int c = t & 15, sub = t >> 4;
    const int warp = t >> 5;
    const int mh_local = c & 3, gate = c >> 2;
    const int m = gate*HLL + blk*4 + mh_local;

    float w[32];
    {
        const float* wr = Whh + (long)m*HLL + sub*32;
        #pragma unroll
        for (int j = 0; j < 32; j++) w[j] = wr[j];
    }

    const int ub = t & 15;
    const int uml = (t >> 4) & 3;
    const int umh = blk*4 + uml;
    float creg = 0.0f;
    float bi = 0.f, bf = 0.f, bg = 0.f, bo = 0.f;
    if (t < 64) {
        bi = bhh[0*HLL + umh]; bf = bhh[1*HLL + umh];
        bg = bhh[2*HLL + umh]; bo = bhh[3*HLL + umh];
    }

    for (int i = t; i < HLL*BB; i += LTHR) (&hs[0][0])[i] = 0.0f;
    __syncthreads();

    unsigned target = 0;

    for (int step = 0; step < TT; step++) {
        float zi = 0.f, zf = 0.f, zg = 0.f, zo = 0.f;
        if (t < 64) {
            long zb = ((long)ub*TT + step)*G4;
            zi = __ldcs(&Z[zb + 0*HLL + umh]); zf = __ldcs(&Z[zb + 1*HLL + umh]);
            zg = __ldcs(&Z[zb + 2*HLL + umh]); zo = __ldcs(&Z[zb + 3*HLL + umh]);
        }

        float acc[BB];
        #pragma unroll
        for (int b = 0; b < BB; b++) acc[b] = 0.0f;
        #pragma unroll
        for (int j = 0; j < 32; j++) {
            float wv = w[j];
            const float* hr = &hs[sub*32 + j][0];
            #pragma unroll
            for (int b = 0; b < BB; b += 4) {
                float4 h4 = *(const float4*)&hr[b];
                acc[b+0] += wv*h4.x; acc[b+1] += wv*h4.y;
                acc[b+2] += wv*h4.z; acc[b+3] += wv*h4.w;
            }
        }
        #pragma unroll
        for (int b = 0; b < BB; b++)
            acc[b] += __shfl_down_sync(0xffffffffu, acc[b], 16);
        if ((t & 31) < 16) {
            float* rp = &red[(warp*16 + c)*17];
            #pragma unroll
            for (int b = 0; b < BB; b++) rp[b] = acc[b];
        }
        __syncthreads();
        {
            int c2 = t & 15, b2 = t >> 4;
            float s = 0.0f;
            #pragma unroll
            for (int s2 = 0; s2 < 8; s2++) s += red[(s2*16 + c2)*17 + b2];
            gsum[c2*16 + b2] = s;
        }
        __syncthreads();

        if (t < 64) {
            float gi = sigf (zi + gsum[(0*4+uml)*16 + ub] + bi);
            float gf = sigf (zf + gsum[(1*4+uml)*16 + ub] + bf);
            float gg = tanhf(zg + gsum[(2*4+uml)*16 + ub] + bg);
            float go = sigf (zo + gsum[(3*4+uml)*16 + ub] + bo);
            creg = gf*creg + gi*gg;
            float hn = go*tanhf(creg);
            float* hout = ((step+1) & 1) ? bufB : bufA;
            stcg(&hout[umh*BB + ub], hn);
            if (WRITE_Y) y16[((long)ub*TT + step)*HLL + umh] = __float2half(hn);
            __threadfence();
        }
        __syncthreads();

        target += LBLK;
        if (t == 0) {
            atomicAdd(bar, 1u);
            while (*(volatile unsigned*)bar < target) { }
        }
        __syncthreads();

        if (step + 1 < TT) {
            const float4* hin = (const float4*)(((step+1) & 1) ? bufB : bufA);
            float4* hsd = (float4*)&hs[0][0];
            #pragma unroll
            for (int q = t; q < HLL*BB/4; q += LTHR)
                hsd[q] = ldcg4(&hin[q]);
            __syncthreads();
        }
    }
}

// ---------------- final projection (h in [j][b] layout) ----------------
__global__ void proj_kernel(const float* __restrict__ h, const float* __restrict__ Wp,
                            const float* __restrict__ bp, float* __restrict__ out)
{
    int tid = threadIdx.x;
    int b = tid >> 3, o = tid & 7;
    float s = bp[o];
    const float* wr = Wp + o*HLL;
    for (int m = 0; m < HLL; m++) s += h[m*BB + b]*wr[m];
    out[b*8 + o] = s;
}

// ---------------- launch ----------------
extern "C" void kernel_launch(void* const* d_in, const int* in_sizes, int n_in,
                              void* d_out, int out_size)
{
    const float* x    = (const float*)d_in[0];
    const float* adj  = (const float*)d_in[1];
    const float* W1   = (const float*)d_in[2];
    const float* b1   = (const float*)d_in[3];
    const float* W2   = (const float*)d_in[4];
    const float* b2   = (const float*)d_in[5];
    const float* gn1w = (const float*)d_in[6];
    const float* gn1b = (const float*)d_in[7];
    const float* gn1m = (const float*)d_in[8];
    const float* gn2w = (const float*)d_in[9];
    const float* gn2b = (const float*)d_in[10];
    const float* gn2m = (const float*)d_in[11];
    const float* Wih0 = (const float*)d_in[12];
    const float* Whh0 = (const float*)d_in[13];
    const float* bih0 = (const float*)d_in[14];
    const float* bhh0 = (const float*)d_in[15];
    const float* Wih1 = (const float*)d_in[16];
    const float* Whh1 = (const float*)d_in[17];
    const float* bih1 = (const float*)d_in[18];
    const float* bhh1 = (const float*)d_in[19];
    const float* Wp   = (const float*)d_in[20];
    const float* bp   = (const float*)d_in[21];
    float* out = (float*)d_out;

    float *pD, *pTmp, *pH1, *pZ0, *pZ1, *pHA0, *pHB0, *pHA1, *pHB1;
    unsigned* pBars;
    __half *pX16, *pHw16, *pH116, *pH216, *pW116, *pW216, *pWih016, *pWih116, *pM16, *pY016;
    cudaGetSymbolAddress((void**)&pD,     g_d);
    cudaGetSymbolAddress((void**)&pTmp,   g_tmp);
    cudaGetSymbolAddress((void**)&pH1,    g_h1);
    cudaGetSymbolAddress((void**)&pZ0,    g_Z0);
    cudaGetSymbolAddress((void**)&pZ1,    g_Z1);
    cudaGetSymbolAddress((void**)&pHA0,   g_hA0);
    cudaGetSymbolAddress((void**)&pHB0,   g_hB0);
    cudaGetSymbolAddress((void**)&pHA1,   g_hA1);
    cudaGetSymbolAddress((void**)&pHB1,   g_hB1);
    cudaGetSymbolAddress((void**)&pBars,  g_bars);
    cudaGetSymbolAddress((void**)&pX16,   g_x16);
    cudaGetSymbolAddress((void**)&pHw16,  g_hw16);
    cudaGetSymbolAddress((void**)&pH116,  g_h116);
    cudaGetSymbolAddress((void**)&pH216,  g_h216);
    cudaGetSymbolAddress((void**)&pW116,  g_W116);
    cudaGetSymbolAddress((void**)&pW216,  g_W216);
    cudaGetSymbolAddress((void**)&pWih016,g_Wih016);
    cudaGetSymbolAddress((void**)&pWih116,g_Wih116);
    cudaGetSymbolAddress((void**)&pM16,   g_M16);
    cudaGetSymbolAddress((void**)&pY016,  g_y016);

    cudaFuncSetAttribute(hgemm<true>,  cudaFuncAttributeMaxDynamicSharedMemorySize, HSMEM);
    cudaFuncSetAttribute(hgemm<false>, cudaFuncAttributeMaxDynamicSharedMemorySize, HSMEM);

    // converts + M + barrier reset
    f2h_kernel<<<32768, 256>>>(x, pX16, (long)BB*TT*NN_*CC);
    f2h_kernel<<<512, 256>>>(W1, pW116, (long)TT*CC*HH);
    f2h_kernel<<<512, 256>>>(W2, pW216, (long)TT*HH*HH);
    f2h_kernel<<<131072, 256>>>(Wih0, pWih016, (long)G4*DD);
    f2h_kernel<<<1024, 256>>>(Wih1, pWih116, (long)G4*HLL);
    deg_kernel<<<2, 256>>>(adj, pD);
    buildM_kernel<<<(NN_*NN_)/256, 256>>>(adj, pD, pM16);
    zero_bars_kernel<<<1, 32>>>(pBars);

    const long sX = (long)NN_*HH;   // 65536
    const int  BT = BB*TT;          // 512
    const long zTot = (long)BT*G4;  // 1,048,576

    // ---- GCN layer 1 ----
    hgemm<true><<<dim3(1, NN_/HBM, BT), 256, HSMEM>>>(pX16, pW116, nullptr, nullptr, pHw16,
        NN_, HH, CC, sX, BT, (long)CC*HH, TT, 0, 1, sX, 1, 0);
    hgemm<true><<<dim3(1, NN_/HBM, BT), 256, HSMEM>>>(pM16, pHw16, b1, pTmp, nullptr,
        NN_, HH, NN_, 0, 1, sX, BT, HH, TT, sX, 1, 0);
    graphnorm_kernel<<<(int)(TNH/256), 256>>>(pTmp, x, gn1w, gn1b, gn1m, pH1, pH116);

    // ---- GCN layer 2 ----
    hgemm<true><<<dim3(1, NN_/HBM, BT), 256, HSMEM>>>(pH116, pW216, nullptr, nullptr, pHw16,
        NN_, HH, HH, sX, BT, (long)HH*HH, TT, 0, 1, sX, 1, 0);
    hgemm<true><<<dim3(1, NN_/HBM, BT), 256, HSMEM>>>(pM16, pHw16, b2, pTmp, nullptr,
        NN_, HH, NN_, 0, 1, sX, BT, HH, TT, sX, 1, 0);
    graphnorm_kernel<<<(int)(TNH/256), 256>>>(pTmp, pH1, gn2w, gn2b, gn2m, nullptr, pH216);

    // ---- LSTM layer 0: Z0 GEMM (split-K=8, partials in g_tmp), reduce, recurrence ----
    hgemm<false><<<dim3(G4/HBN, BT/HBM, SPLITK0), 256, HSMEM>>>(pH216, pWih016, nullptr, pTmp, nullptr,
        BT, G4, DD, 0, 1, 0, 1, 0, 1, 0, SPLITK0, zTot);
    reduce_bias_kernel<<<(int)(zTot/256), 256>>>(pTmp, bih0, pZ0, zTot, zTot, SPLITK0);
    lstm_persistent<true><<<LBLK, LTHR>>>(pZ0, Whh0, bhh0, pHA0, pHB0, pY016, pBars + 0);

    // ---- LSTM layer 1 ----
    hgemm<false><<<dim3(G4/HBN, BT/HBM, SPLITK1), 256, HSMEM>>>(pY016, pWih116, nullptr, pTmp, nullptr,
        BT, G4, HLL, 0, 1, 0, 1, 0, 1, 0, SPLITK1, zTot);
    reduce_bias_kernel<<<(int)(zTot/256), 256>>>(pTmp, bih1, pZ1, zTot, zTot, SPLITK1);
    lstm_persistent<false><<<LBLK, LTHR>>>(pZ1, Whh1, bhh1, pHA1, pHB1, nullptr, pBars + 1);

    // ---- projection ----
    proj_kernel<<<1, 128>>>(pHA1, Wp, bp, out);
}